// round 14
// baseline (speedup 1.0000x reference)
#include <cuda_runtime.h>
#include <cuda_bf16.h>
#include <stdint.h>
#include <math.h>
#define D 128
#define DOUT 64
#define NP 30000
#define EA 300000
#define EP 960000
#define B 16384
#define NEG 0.2f
typedef unsigned long long u64;
typedef unsigned int u32;

__device__ float g_xlpp[NP*D];
__device__ float g_xrpp[B*D];
__device__ float g_xrap[B*D];
__device__ float g_hid[B*D];
__device__ float g_acc[B*D];
__device__ float g_ppo[B*D];
__device__ float g_lg[EA];
__device__ float g_lgp[EP];
__device__ u64 g_Bfh[4096];
__device__ u64 g_Bfl[4096];
__device__ int g_ca[B], g_cp[B], g_oa[B+1], g_op[B+1], g_ua[B], g_up[B];
__device__ int g_sa[EA], g_da[EA], g_sp[EP], g_dp[EP];

__device__ __forceinline__ float lrelu(float x){ return x>0.f?x:NEG*x; }
__device__ __forceinline__ u64 splat2(float x){ u64 d; asm("mov.b64 %0,{%1,%1};":"=l"(d):"r"(__float_as_uint(x))); return d; }
__device__ __forceinline__ u64 pack2(float a,float b){ u64 d; asm("mov.b64 %0,{%1,%2};":"=l"(d):"r"(__float_as_uint(a)),"r"(__float_as_uint(b))); return d; }
__device__ __forceinline__ float2 unpack2(u64 u){ float2 f; asm("mov.b64 {%0,%1},%2;":"=f"(f.x),"=f"(f.y):"l"(u)); return f; }
__device__ __forceinline__ u64 ffma2(u64 a,u64 b,u64 c){ u64 d; asm("fma.rn.f32x2 %0,%1,%2,%3;":"=l"(d):"l"(a),"l"(b),"l"(c)); return d; }
__device__ __forceinline__ u32 cbf2(float lo,float hi){ u32 r; asm("cvt.rn.bf16x2.f32 %0,%1,%2;":"=r"(r):"f"(hi),"f"(lo)); return r; }
__device__ __forceinline__ float blo(u32 r){ return __uint_as_float(r<<16); }
__device__ __forceinline__ float bhi(u32 r){ return __uint_as_float(r&0xffff0000u); }
__device__ __forceinline__ void mmab(float* c,u32 a0,u32 a1,u32 a2,u32 a3,u32 b0,u32 b1){
    asm volatile("mma.sync.aligned.m16n8k16.row.col.f32.bf16.bf16.f32 "
        "{%0,%1,%2,%3},{%4,%5,%6,%7},{%8,%9},{%0,%1,%2,%3};"
        :"+f"(c[0]),"+f"(c[1]),"+f"(c[2]),"+f"(c[3])
        :"r"(a0),"r"(a1),"r"(a2),"r"(a3),"r"(b0),"r"(b1));
}

__global__ void k_zero(int* a,int* b,const float* W,u64* fh,u64* fl){
    int i=blockIdx.x*blockDim.x+threadIdx.x;
    if(i<B) a[i]=0;
    else if(i<2*B) b[i-B]=0;
    else if(i<2*B+4096){
        int idx=i-2*B;
        int ks=idx>>9, j=(idx>>5)&15, ln=idx&31;
        int n=8*j+(ln>>2), kw=ks*8+(ln&3);
        float v00=W[(2*kw)*128+n],   v01=W[(2*kw+1)*128+n];
        float v10=W[(2*kw+8)*128+n], v11=W[(2*kw+9)*128+n];
        u32 w0=cbf2(v00,v01), w1=cbf2(v10,v11);
        u32 g0=cbf2(v00-blo(w0),v01-bhi(w0));
        u32 g1=cbf2(v10-blo(w1),v11-bhi(w1));
        fh[idx]=(u64)w0|((u64)w1<<32);
        fl[idx]=(u64)g0|((u64)g1<<32);
    }
}
__global__ void k_hist(const int* ea,int Ea,int* ca,const int* ep,int Ep,int* cp){
    int i=blockIdx.x*blockDim.x+threadIdx.x;
    if(i<Ea){ int d=ea[Ea+i]; if(d<B) atomicAdd(&ca[d],1); }
    else if(i<Ea+Ep){ int d=ep[Ep+i-Ea]; if(d<B) atomicAdd(&cp[d],1); }
}
__global__ void k_scan(const int* ca,int* oa,int* ua,const int* cp,int* op,int* up){
    const int* cnt=blockIdx.x?cp:ca;
    int* off=blockIdx.x?op:oa;
    int* cur=blockIdx.x?up:ua;
    __shared__ int s[1024];
    int t=threadIdx.x,v[16],run=0;
#pragma unroll
    for(int i=0;i<16;i++){ v[i]=run; run+=cnt[t*16+i]; }
    s[t]=run; __syncthreads();
    for(int d=1;d<1024;d<<=1){
        int add=(t>=d)?s[t-d]:0; __syncthreads();
        s[t]+=add; __syncthreads();
    }
    int base=(t>0)?s[t-1]:0;
#pragma unroll
    for(int i=0;i<16;i++){ int o=base+v[i]; off[t*16+i]=o; cur[t*16+i]=o; }
    if(t==1023) off[16384]=s[1023];
}
__global__ void k_scat(const int* ea,int Ea,int* ua,int* sa,int* da,
                       const int* ep,int Ep,int* up,int* sp,int* dp){
    int i=blockIdx.x*blockDim.x+threadIdx.x;
    if(i<Ea){
        int d=ea[Ea+i];
        if(d<B){ int p=atomicAdd(&ua[d],1); sa[p]=ea[i]; da[p]=d; }
    } else if(i<Ea+Ep){
        int j=i-Ea; int d=ep[Ep+j];
        if(d<B){ int p=atomicAdd(&up[d],1); sp[p]=ep[j]; dp[p]=d; }
    }
}

// PP logits, edge-parallel: 4 lanes per edge, 8 edges per warp
__global__ void __launch_bounds__(256) k_plg(
    const float* __restrict__ xlpp,const float* __restrict__ xrpp,
    const float* __restrict__ att,const int* __restrict__ sp,
    const int* __restrict__ dp,const int* __restrict__ totp,
    float* __restrict__ lgp){
    int total=*totp;
    int w=blockIdx.x*8+(threadIdx.x>>5);
    if(w*8>=total) return;
    int lane=threadIdx.x&31;
    int ei=w*8+(lane>>2),sub=lane&3;
    bool valid=ei<total;
    int s=valid?sp[ei]:0,d=valid?dp[ei]:0;
    const float4* XL=(const float4*)xlpp+(size_t)s*32+sub*8;
    const float4* XR=(const float4*)xrpp+(size_t)d*32+sub*8;
    const float4* AT=(const float4*)att+sub*8;
    float p=0.f;
#pragma unroll
    for(int j=0;j<8;j++){
        float4 a=AT[j],x=XL[j],r=XR[j];
        p+=a.x*lrelu(x.x+r.x)+a.y*lrelu(x.y+r.y)+a.z*lrelu(x.z+r.z)+a.w*lrelu(x.w+r.w);
    }
    p+=__shfl_xor_sync(0xffffffffu,p,1);
    p+=__shfl_xor_sync(0xffffffffu,p,2);
    if(sub==0&&valid) lgp[ei]=p;
}

// edge logits via HMMA bf16-split (round-12 config: K-split, 2 CTA/SM)
__global__ void __launch_bounds__(256,2) k_emma(
    const float* __restrict__ xa,const u64* __restrict__ Bfh,const u64* __restrict__ Bfl,
    const float* __restrict__ blv,const int* __restrict__ srcs,const int* __restrict__ tot,
    const int* __restrict__ darr,const float* __restrict__ xr,
    const float* __restrict__ att,float* __restrict__ lg){
    extern __shared__ char sm[];
    u32* ah=(u32*)sm;
    u32* al=ah+4608;
    u64* bh=(u64*)(al+4608);
    u64* bw=bh+2048;
    int total=*tot;
    int row0=blockIdx.x*128;
    if(row0>=total) return;
    int t=threadIdx.x,wid=t>>5,lane=t&31;
    int g=lane>>2,tt=lane&3,m0=wid*16;
    int m=t>>1,q=t&1;
    int r=row0+m;
    int rr=(r<total)?srcs[r]:0;
    const float4* X4=(const float4*)xa;
    int rA=(m0+g)*36,rB=rA+288;
    float P[16][4];
#pragma unroll
    for(int j=0;j<16;j++){ P[j][0]=0.f;P[j][1]=0.f;P[j][2]=0.f;P[j][3]=0.f; }
#pragma unroll
    for(int h2=0;h2<2;h2++){
        if(h2) __syncthreads();
        {
            int base=m*36+q*16;
#pragma unroll
            for(int j=0;j<8;j++){
                float4 v=X4[(size_t)rr*32+h2*16+q*8+j];
                u32 w0=cbf2(v.x,v.y),w1=cbf2(v.z,v.w);
                u32 g0=cbf2(v.x-blo(w0),v.y-bhi(w0));
                u32 g1=cbf2(v.z-blo(w1),v.w-bhi(w1));
                ah[base+2*j]=w0; ah[base+2*j+1]=w1;
                al[base+2*j]=g0; al[base+2*j+1]=g1;
            }
        }
        for(int i=t;i<1024;i+=256){
            ((uint4*)bh)[i]=((const uint4*)Bfh)[h2*1024+i];
            ((uint4*)bw)[i]=((const uint4*)Bfl)[h2*1024+i];
        }
        __syncthreads();
#pragma unroll
        for(int ksl=0;ksl<4;ksl++){
            int kb=ksl*8+tt;
            u32 a0=ah[rA+kb],a1=ah[rB+kb],a2=ah[rA+kb+4],a3=ah[rB+kb+4];
            u32 l0=al[rA+kb],l1=al[rB+kb],l2=al[rA+kb+4],l3=al[rB+kb+4];
            const u64* bp=bh+ksl*512+lane;
            const u64* cp2=bw+ksl*512+lane;
#pragma unroll
            for(int j=0;j<16;j++){
                u64 bb=bp[j*32];
                mmab(P[j],a0,a1,a2,a3,(u32)bb,(u32)(bb>>32));
            }
#pragma unroll
            for(int j=0;j<16;j++){
                u64 cc=cp2[j*32];
                mmab(P[j],a0,a1,a2,a3,(u32)cc,(u32)(cc>>32));
            }
#pragma unroll
            for(int j=0;j<16;j++){
                u64 bb=bp[j*32];
                mmab(P[j],l0,l1,l2,l3,(u32)bb,(u32)(bb>>32));
            }
        }
    }
    int ra=row0+m0+g,rb=ra+8;
    int dda=(ra<total)?darr[ra]:0,ddb=(rb<total)?darr[rb]:0;
    const float2* XRa=(const float2*)xr+(size_t)dda*64;
    const float2* XRb=(const float2*)xr+(size_t)ddb*64;
    const float2* AT=(const float2*)att;
    const float2* BL=(const float2*)blv;
    float pa=0.f,pb=0.f;
#pragma unroll
    for(int j=0;j<16;j++){
        int ci=j*4+tt;
        float2 av=AT[ci],bv=BL[ci],x1=XRa[ci],x2=XRb[ci];
        pa+=av.x*lrelu(P[j][0]+bv.x+x1.x)+av.y*lrelu(P[j][1]+bv.y+x1.y);
        pb+=av.x*lrelu(P[j][2]+bv.x+x2.x)+av.y*lrelu(P[j][3]+bv.y+x2.y);
    }
    pa+=__shfl_xor_sync(0xffffffffu,pa,1); pa+=__shfl_xor_sync(0xffffffffu,pa,2);
    pb+=__shfl_xor_sync(0xffffffffu,pb,1); pb+=__shfl_xor_sync(0xffffffffu,pb,2);
    if(tt==0){
        if(ra<total) lg[ra]=pa;
        if(rb<total) lg[rb]=pb;
    }
}

// fp32 128x128 GEMM, k-chunk double-buffered. MODE 0: Y=X@W+b1; MODE 2: +b2+addmat
template <int MODE>
__global__ void __launch_bounds__(256) k_gemm(
    const float* __restrict__ X,const float* __restrict__ W,
    const float* __restrict__ b1,const float* __restrict__ b2,
    float* __restrict__ Y,int total,const float* __restrict__ am){
    int row0=blockIdx.x*128;
    if(row0>=total) return;
    __shared__ float Ws[2][16][128];
    __shared__ float Xs[2][16][128];
    int t=threadIdx.x,tx=t&15,ty=t>>4;
    int tx8=tx*8,ty8=ty*8;
    int ma=t>>2,kq=t&3,mb=ma+64;
    int kwa=t>>5,nw=t&31,kwb=kwa+8;
    int rra=(row0+ma<total)?row0+ma:0;
    int rrb=(row0+mb<total)?row0+mb:0;
    const float4* X4=(const float4*)X;
    const float4* W4=(const float4*)W;
    u64 acc[8][4];
    {
        float4 q0=((const float4*)b1)[tx*2],q1=((const float4*)b1)[tx*2+1];
        if(MODE==2){
            float4 p0=((const float4*)b2)[tx*2],p1=((const float4*)b2)[tx*2+1];
            q0.x+=p0.x;q0.y+=p0.y;q0.z+=p0.z;q0.w+=p0.w;
            q1.x+=p1.x;q1.y+=p1.y;q1.z+=p1.z;q1.w+=p1.w;
        }
        u64 i0=pack2(q0.x,q0.y),i1=pack2(q0.z,q0.w),i2=pack2(q1.x,q1.y),i3=pack2(q1.z,q1.w);
#pragma unroll
        for(int r=0;r<8;r++){ acc[r][0]=i0;acc[r][1]=i1;acc[r][2]=i2;acc[r][3]=i3; }
    }
    float4 va=X4[(size_t)rra*32+kq];
    float4 vb=X4[(size_t)rrb*32+kq];
    float4 wa=W4[kwa*32+nw];
    float4 wb=W4[kwb*32+nw];
    ((float4*)&Ws[0][kwa][nw*4])[0]=wa;
    ((float4*)&Ws[0][kwb][nw*4])[0]=wb;
    Xs[0][kq*4+0][ma]=va.x; Xs[0][kq*4+1][ma]=va.y; Xs[0][kq*4+2][ma]=va.z; Xs[0][kq*4+3][ma]=va.w;
    Xs[0][kq*4+0][mb]=vb.x; Xs[0][kq*4+1][mb]=vb.y; Xs[0][kq*4+2][mb]=vb.z; Xs[0][kq*4+3][mb]=vb.w;
    __syncthreads();
#pragma unroll
    for(int c=0;c<8;c++){
        int buf=c&1;
        if(c<7){
            va=X4[(size_t)rra*32+(c+1)*4+kq];
            vb=X4[(size_t)rrb*32+(c+1)*4+kq];
            wa=W4[((c+1)*16+kwa)*32+nw];
            wb=W4[((c+1)*16+kwb)*32+nw];
        }
#pragma unroll
        for(int kk=0;kk<16;kk++){
            float4 a0=*(const float4*)&Xs[buf][kk][ty8];
            float4 a1=*(const float4*)&Xs[buf][kk][ty8+4];
            ulonglong2 b01=*(const ulonglong2*)&Ws[buf][kk][tx8];
            ulonglong2 b23=*(const ulonglong2*)&Ws[buf][kk][tx8+4];
            float av[8]={a0.x,a0.y,a0.z,a0.w,a1.x,a1.y,a1.z,a1.w};
#pragma unroll
            for(int r=0;r<8;r++){
                u64 s=splat2(av[r]);
                acc[r][0]=ffma2(s,b01.x,acc[r][0]);
                acc[r][1]=ffma2(s,b01.y,acc[r][1]);
                acc[r][2]=ffma2(s,b23.x,acc[r][2]);
                acc[r][3]=ffma2(s,b23.y,acc[r][3]);
            }
        }
        if(c<7){
            int nb=buf^1;
            ((float4*)&Ws[nb][kwa][nw*4])[0]=wa;
            ((float4*)&Ws[nb][kwb][nw*4])[0]=wb;
            Xs[nb][kq*4+0][ma]=va.x; Xs[nb][kq*4+1][ma]=va.y; Xs[nb][kq*4+2][ma]=va.z; Xs[nb][kq*4+3][ma]=va.w;
            Xs[nb][kq*4+0][mb]=vb.x; Xs[nb][kq*4+1][mb]=vb.y; Xs[nb][kq*4+2][mb]=vb.z; Xs[nb][kq*4+3][mb]=vb.w;
            __syncthreads();
        }
    }
#pragma unroll
    for(int r=0;r<8;r++){
        int row=row0+ty8+r;
        if(row<total){
            float2 v0=unpack2(acc[r][0]),v1=unpack2(acc[r][1]),v2=unpack2(acc[r][2]),v3=unpack2(acc[r][3]);
            float4 o0=make_float4(v0.x,v0.y,v1.x,v1.y);
            float4 o1=make_float4(v2.x,v2.y,v3.x,v3.y);
            if(MODE==2){
                float4 m0=((const float4*)am)[(size_t)row*32+tx*2];
                float4 m1=((const float4*)am)[(size_t)row*32+tx*2+1];
                o0.x+=m0.x;o0.y+=m0.y;o0.z+=m0.z;o0.w+=m0.w;
                o1.x+=m1.x;o1.y+=m1.y;o1.z+=m1.z;o1.w+=m1.w;
            }
            ((float4*)Y)[(size_t)row*32+tx*2]=o0;
            ((float4*)Y)[(size_t)row*32+tx*2+1]=o1;
        }
    }
}

// two-pass weighted gather: pass1 logit max/denom (coalesced), pass2 gather
__device__ __forceinline__ float4 wsum(
    const float* __restrict__ X,const float* __restrict__ L,
    const int* __restrict__ idx,int e0,int e1,int lane){
    float4 acc=make_float4(0.f,0.f,0.f,0.f);
    if(e1<=e0) return acc;
    float m=-INFINITY,den=0.f;
    for(int base=e0;base<e1;base+=32){
        int e=base+lane;
        bool v=(e<e1);
        float le=v?L[e]:-INFINITY;
        float cm=le;
#pragma unroll
        for(int o=16;o;o>>=1) cm=fmaxf(cm,__shfl_xor_sync(0xffffffffu,cm,o));
        if(cm>m){ den*=__expf(m-cm); m=cm; }
        float w=v?__expf(le-m):0.f;
#pragma unroll
        for(int o=16;o;o>>=1) w+=__shfl_xor_sync(0xffffffffu,w,o);
        den+=w;
    }
    float inv=1.f/den;
    int e=e0;
    for(;e+3<e1;e+=4){
        int s0=idx[e],s1=idx[e+1],s2=idx[e+2],s3=idx[e+3];
        float4 x0=((const float4*)X)[(size_t)s0*32+lane];
        float4 x1=((const float4*)X)[(size_t)s1*32+lane];
        float4 x2=((const float4*)X)[(size_t)s2*32+lane];
        float4 x3=((const float4*)X)[(size_t)s3*32+lane];
        float a0=__expf(L[e]-m)*inv,a1=__expf(L[e+1]-m)*inv;
        float a2=__expf(L[e+2]-m)*inv,a3=__expf(L[e+3]-m)*inv;
        acc.x+=a0*x0.x+a1*x1.x+a2*x2.x+a3*x3.x;
        acc.y+=a0*x0.y+a1*x1.y+a2*x2.y+a3*x3.y;
        acc.z+=a0*x0.z+a1*x1.z+a2*x2.z+a3*x3.z;
        acc.w+=a0*x0.w+a1*x1.w+a2*x2.w+a3*x3.w;
    }
    for(;e<e1;e++){
        float a0=__expf(L[e]-m)*inv;
        float4 x0=((const float4*)X)[(size_t)idx[e]*32+lane];
        acc.x+=a0*x0.x; acc.y+=a0*x0.y; acc.z+=a0*x0.z; acc.w+=a0*x0.w;
    }
    return acc;
}

__global__ void __launch_bounds__(256) k_agg(
    const float* __restrict__ xa,const float* __restrict__ lg,
    const int* __restrict__ oa,const int* __restrict__ sa,
    const float* __restrict__ xlpp,const float* __restrict__ lgp,
    const int* __restrict__ op,const int* __restrict__ sp,
    const float* __restrict__ bsp,
    float* __restrict__ accap,float* __restrict__ ppo){
    int t=threadIdx.x,lane=t&31,warp=t>>5;
    int dst=blockIdx.x*8+warp;
    float4 a=wsum(xa,lg,sa,oa[dst],oa[dst+1],lane);
    ((float4*)accap)[(size_t)dst*32+lane]=a;
    float4 p=wsum(xlpp,lgp,sp,op[dst],op[dst+1],lane);
    float4 bs=((const float4*)bsp)[lane];
    p.x+=bs.x; p.y+=bs.y; p.z+=bs.z; p.w+=bs.w;
    ((float4*)ppo)[(size_t)dst*32+lane]=p;
}

__global__ void __launch_bounds__(256) k_final(
    const float* __restrict__ hid,const float* __restrict__ Wl,
    const float* __restrict__ bl,float* __restrict__ out){
    extern __shared__ char sm[];
    float* Ws=(float*)sm;
    float* hs=(float*)sm+D*DOUT;
    int t=threadIdx.x,lane=t&31,warp=t>>5;
    for(int i=t;i<D*DOUT/4;i+=256) ((float4*)Ws)[i]=((const float4*)Wl)[i];
    int row0=blockIdx.x*32+warp*4;
#pragma unroll
    for(int r=0;r<4;r++){
        float4 h=((const float4*)hid)[(size_t)(row0+r)*32+lane];
        h.x=fmaxf(h.x,0.f); h.y=fmaxf(h.y,0.f); h.z=fmaxf(h.z,0.f); h.w=fmaxf(h.w,0.f);
        ((float4*)&hs[(warp*4+r)*D])[lane]=h;
    }
    __syncthreads();
    float b0=bl[lane],b1=bl[lane+32];
    float a0[4],a1[4];
#pragma unroll
    for(int r=0;r<4;r++){ a0[r]=b0; a1[r]=b1; }
    for(int k=0;k<D;k++){
        float w0=Ws[k*DOUT+lane],w1=Ws[k*DOUT+lane+32];
#pragma unroll
        for(int r=0;r<4;r++){
            float h=hs[(warp*4+r)*D+k];
            a0[r]+=h*w0; a1[r]+=h*w1;
        }
    }
#pragma unroll
    for(int r=0;r<4;r++){
        int row=row0+r;
        out[(size_t)row*DOUT+lane]=a0[r];
        out[(size_t)row*DOUT+lane+32]=a1[r];
    }
}

extern "C" void kernel_launch(void* const* d_in,const int* in_sizes,int n_in,
                              void* d_out,int out_size){
    const float* xa=(const float*)d_in[0];
    const float* xp=(const float*)d_in[1];
    const int* ea=(const int*)d_in[2];
    const int* ep=(const int*)d_in[3];
    const float* Wla=(const float*)d_in[5];
    const float* bla=(const float*)d_in[6];
    const float* Wra=(const float*)d_in[7];
    const float* bra=(const float*)d_in[8];
    const float* ata=(const float*)d_in[9];
    const float* bsa=(const float*)d_in[10];
    const float* Wlp=(const float*)d_in[11];
    const float* blp=(const float*)d_in[12];
    const float* Wrp=(const float*)d_in[13];
    const float* brp=(const float*)d_in[14];
    const float* atp=(const float*)d_in[15];
    const float* bsp=(const float*)d_in[16];
    const float* Wf=(const float*)d_in[17];
    const float* bf=(const float*)d_in[18];
    float* out=(float*)d_out;
    int Ea=in_sizes[2]/2,Ep=in_sizes[3]/2,Eb=Ea+Ep;

    void* p;
    cudaGetSymbolAddress(&p,g_xlpp); float* xlpp=(float*)p;
    cudaGetSymbolAddress(&p,g_xrpp); float* xrpp=(float*)p;
    cudaGetSymbolAddress(&p,g_xrap); float* xrap=(float*)p;
    cudaGetSymbolAddress(&p,g_hid);  float* hid=(float*)p;
    cudaGetSymbolAddress(&p,g_acc);  float* accap=(float*)p;
    cudaGetSymbolAddress(&p,g_ppo);  float* ppo=(float*)p;
    cudaGetSymbolAddress(&p,g_lg);   float* lg=(float*)p;
    cudaGetSymbolAddress(&p,g_lgp);  float* lgp=(float*)p;
    cudaGetSymbolAddress(&p,g_Bfh);  u64* Bfh=(u64*)p;
    cudaGetSymbolAddress(&p,g_Bfl);  u64* Bfl=(u64*)p;
    cudaGetSymbolAddress(&p,g_ca);   int* ca=(int*)p;
    cudaGetSymbolAddress(&p,g_cp);   int* cp=(int*)p;
    cudaGetSymbolAddress(&p,g_oa);   int* oa=(int*)p;
    cudaGetSymbolAddress(&p,g_op);   int* op=(int*)p;
    cudaGetSymbolAddress(&p,g_ua);   int* ua=(int*)p;
    cudaGetSymbolAddress(&p,g_up);   int* up=(int*)p;
    cudaGetSymbolAddress(&p,g_sa);   int* sa=(int*)p;
    cudaGetSymbolAddress(&p,g_da);   int* da=(int*)p;
    cudaGetSymbolAddress(&p,g_sp);   int* sp=(int*)p;
    cudaGetSymbolAddress(&p,g_dp);   int* dp=(int*)p;

    cudaFuncSetAttribute(k_emma,cudaFuncAttributeMaxDynamicSharedMemorySize,69632);
    cudaFuncSetAttribute(k_final,cudaFuncAttributeMaxDynamicSharedMemorySize,49152);

    k_zero<<<(2*B+4096+255)/256,256>>>(ca,cp,Wla,Bfh,Bfl);
    k_hist<<<(Eb+255)/256,256>>>(ea,Ea,ca,ep,Ep,cp);
    k_scan<<<2,1024>>>(ca,oa,ua,cp,op,up);
    k_scat<<<(Eb+255)/256,256>>>(ea,Ea,ua,sa,da,ep,Ep,up,sp,dp);
    k_gemm<0><<<B/128,256>>>(xp,Wra,bra,nullptr,xrap,B,nullptr);
    k_emma<<<(EA+127)/128,256,69632>>>(xa,Bfh,Bfl,bla,sa,&oa[B],da,xrap,ata,lg);
    k_gemm<0><<<(NP+127)/128,256>>>(xp,Wlp,blp,nullptr,xlpp,NP,nullptr);
    k_gemm<0><<<B/128,256>>>(xp,Wrp,brp,nullptr,xrpp,B,nullptr);
    k_plg<<<(EP+63)/64,256>>>(xlpp,xrpp,atp,sp,dp,&op[B],lgp);
    k_agg<<<B/8,256>>>(xa,lg,oa,sa,xlpp,lgp,op,sp,bsp,accap,ppo);
    k_gemm<2><<<B/128,256>>>(accap,Wla,bla,bsa,hid,B,ppo);
    k_final<<<B/32,256,49152>>>(hid,Wf,bf,out);
}

// round 15
// speedup vs baseline: 1.1756x; 1.1756x over previous
#include <cuda_runtime.h>
#include <cuda_fp16.h>
#include <stdint.h>
#include <math.h>
#define D 128
#define DOUT 64
#define NP 30000
#define EA 300000
#define EP 960000
#define B 16384
#define NEG 0.2f
typedef unsigned long long u64;
typedef unsigned int u32;

__device__ float g_xlpp[NP*D];
__device__ float g_xrpp[B*D];
__device__ float g_xrap[B*D];
__device__ float g_hid[B*D];
__device__ float g_acc[B*D];
__device__ float g_ppo[B*D];
__device__ float g_lg[EA];
__device__ u64 g_Bf[4096];    // per-lane B fragments [ks][j][lane], fp16(Wla^T)
__device__ int g_ca[B], g_cp[B], g_oa[B+1], g_op[B+1], g_ua[B], g_up[B];
__device__ int g_sa[EA], g_da[EA], g_sp[EP];

__device__ __forceinline__ float lrelu(float x){ return x>0.f?x:NEG*x; }
__device__ __forceinline__ u64 splat2(float x){ u64 d; asm("mov.b64 %0,{%1,%1};":"=l"(d):"r"(__float_as_uint(x))); return d; }
__device__ __forceinline__ u64 pack2(float a,float b){ u64 d; asm("mov.b64 %0,{%1,%2};":"=l"(d):"r"(__float_as_uint(a)),"r"(__float_as_uint(b))); return d; }
__device__ __forceinline__ float2 unpack2(u64 u){ float2 f; asm("mov.b64 {%0,%1},%2;":"=f"(f.x),"=f"(f.y):"l"(u)); return f; }
__device__ __forceinline__ u64 ffma2(u64 a,u64 b,u64 c){ u64 d; asm("fma.rn.f32x2 %0,%1,%2,%3;":"=l"(d):"l"(a),"l"(b),"l"(c)); return d; }
__device__ __forceinline__ u32 cf2(float lo,float hi){
    __half2 h=__floats2half2_rn(lo,hi); return *(u32*)&h;
}
__device__ __forceinline__ float f16lo(u32 r){ __half2 h=*(__half2*)&r; return __low2float(h); }
__device__ __forceinline__ float f16hi(u32 r){ __half2 h=*(__half2*)&r; return __high2float(h); }
__device__ __forceinline__ void mmah(float* c,u32 a0,u32 a1,u32 a2,u32 a3,u32 b0,u32 b1){
    asm volatile("mma.sync.aligned.m16n8k16.row.col.f32.f16.f16.f32 "
        "{%0,%1,%2,%3},{%4,%5,%6,%7},{%8,%9},{%0,%1,%2,%3};"
        :"+f"(c[0]),"+f"(c[1]),"+f"(c[2]),"+f"(c[3])
        :"r"(a0),"r"(a1),"r"(a2),"r"(a3),"r"(b0),"r"(b1));
}

// zero histograms + build single fp16 per-lane B fragment image from Wla [k][n]
__global__ void k_zero(int* a,int* b,const float* W,u64* fh){
    int i=blockIdx.x*blockDim.x+threadIdx.x;
    if(i<B) a[i]=0;
    else if(i<2*B) b[i-B]=0;
    else if(i<2*B+4096){
        int idx=i-2*B;
        int ks=idx>>9, j=(idx>>5)&15, ln=idx&31;
        int n=8*j+(ln>>2), kw=ks*8+(ln&3);
        float v00=W[(2*kw)*128+n],   v01=W[(2*kw+1)*128+n];
        float v10=W[(2*kw+8)*128+n], v11=W[(2*kw+9)*128+n];
        u32 w0=cf2(v00,v01), w1=cf2(v10,v11);
        fh[idx]=(u64)w0|((u64)w1<<32);
    }
}
__global__ void k_hist(const int* ea,int Ea,int* ca,const int* ep,int Ep,int* cp){
    int i=blockIdx.x*blockDim.x+threadIdx.x;
    if(i<Ea){ int d=ea[Ea+i]; if(d<B) atomicAdd(&ca[d],1); }
    else if(i<Ea+Ep){ int d=ep[Ep+i-Ea]; if(d<B) atomicAdd(&cp[d],1); }
}
__global__ void k_scan(const int* ca,int* oa,int* ua,const int* cp,int* op,int* up){
    const int* cnt=blockIdx.x?cp:ca;
    int* off=blockIdx.x?op:oa;
    int* cur=blockIdx.x?up:ua;
    __shared__ int s[1024];
    int t=threadIdx.x,v[16],run=0;
#pragma unroll
    for(int i=0;i<16;i++){ v[i]=run; run+=cnt[t*16+i]; }
    s[t]=run; __syncthreads();
    for(int d=1;d<1024;d<<=1){
        int add=(t>=d)?s[t-d]:0; __syncthreads();
        s[t]+=add; __syncthreads();
    }
    int base=(t>0)?s[t-1]:0;
#pragma unroll
    for(int i=0;i<16;i++){ int o=base+v[i]; off[t*16+i]=o; cur[t*16+i]=o; }
    if(t==1023) off[16384]=s[1023];
}
__global__ void k_scat(const int* ea,int Ea,int* ua,int* sa,int* da,
                       const int* ep,int Ep,int* up,int* sp){
    int i=blockIdx.x*blockDim.x+threadIdx.x;
    if(i<Ea){
        int d=ea[Ea+i];
        if(d<B){ int p=atomicAdd(&ua[d],1); sa[p]=ea[i]; da[p]=d; }
    } else if(i<Ea+Ep){
        int j=i-Ea; int d=ep[Ep+j];
        if(d<B){ int p=atomicAdd(&up[d],1); sp[p]=ep[j]; }
    }
}

// edge logits via HMMA fp16 A-split (Ah*B + Al*B), K-split staging, 2 CTA/SM
__global__ void __launch_bounds__(256,2) k_emma(
    const float* __restrict__ xa,const u64* __restrict__ Bf,
    const float* __restrict__ blv,const int* __restrict__ srcs,const int* __restrict__ tot,
    const int* __restrict__ darr,const float* __restrict__ xr,
    const float* __restrict__ att,float* __restrict__ lg){
    extern __shared__ char sm[];
    u32* ah=(u32*)sm;              // A hi half [128][36 words] = 18432 B
    u32* al=ah+4608;               // A lo residual half
    u64* bh=(u64*)(al+4608);       // B frag half: 2048 u64 = 16384 B
    int total=*tot;
    int row0=blockIdx.x*128;
    if(row0>=total) return;
    int t=threadIdx.x,wid=t>>5,lane=t&31;
    int g=lane>>2,tt=lane&3,m0=wid*16;
    int m=t>>1,q=t&1;
    int r=row0+m;
    int rr=(r<total)?srcs[r]:0;
    const float4* X4=(const float4*)xa;
    int rA=(m0+g)*36,rB=rA+288;
    float P[16][4];
#pragma unroll
    for(int j=0;j<16;j++){ P[j][0]=0.f;P[j][1]=0.f;P[j][2]=0.f;P[j][3]=0.f; }
#pragma unroll
    for(int h2=0;h2<2;h2++){
        if(h2) __syncthreads();
        {
            int base=m*36+q*16;
#pragma unroll
            for(int j=0;j<8;j++){
                float4 v=X4[(size_t)rr*32+h2*16+q*8+j];
                u32 w0=cf2(v.x,v.y),w1=cf2(v.z,v.w);
                u32 g0=cf2(v.x-f16lo(w0),v.y-f16hi(w0));
                u32 g1=cf2(v.z-f16lo(w1),v.w-f16hi(w1));
                ah[base+2*j]=w0; ah[base+2*j+1]=w1;
                al[base+2*j]=g0; al[base+2*j+1]=g1;
            }
        }
        for(int i=t;i<1024;i+=256){
            ((uint4*)bh)[i]=((const uint4*)Bf)[h2*1024+i];
        }
        __syncthreads();
#pragma unroll
        for(int ksl=0;ksl<4;ksl++){
            int kb=ksl*8+tt;
            u32 a0=ah[rA+kb],a1=ah[rB+kb],a2=ah[rA+kb+4],a3=ah[rB+kb+4];
            u32 l0=al[rA+kb],l1=al[rB+kb],l2=al[rA+kb+4],l3=al[rB+kb+4];
            const u64* bp=bh+ksl*512+lane;
            // phase 1: Ah*B (16 independent chains)
#pragma unroll
            for(int j=0;j<16;j++){
                u64 bb=bp[j*32];
                mmah(P[j],a0,a1,a2,a3,(u32)bb,(u32)(bb>>32));
            }
            // phase 2: Al*B (same-acc reuse distance 16)
#pragma unroll
            for(int j=0;j<16;j++){
                u64 bb=bp[j*32];
                mmah(P[j],l0,l1,l2,l3,(u32)bb,(u32)(bb>>32));
            }
        }
    }
    int ra=row0+m0+g,rb=ra+8;
    int dda=(ra<total)?darr[ra]:0,ddb=(rb<total)?darr[rb]:0;
    const float2* XRa=(const float2*)xr+(size_t)dda*64;
    const float2* XRb=(const float2*)xr+(size_t)ddb*64;
    const float2* AT=(const float2*)att;
    const float2* BL=(const float2*)blv;
    float pa=0.f,pb=0.f;
#pragma unroll
    for(int j=0;j<16;j++){
        int ci=j*4+tt;
        float2 av=AT[ci],bv=BL[ci],x1=XRa[ci],x2=XRb[ci];
        pa+=av.x*lrelu(P[j][0]+bv.x+x1.x)+av.y*lrelu(P[j][1]+bv.y+x1.y);
        pb+=av.x*lrelu(P[j][2]+bv.x+x2.x)+av.y*lrelu(P[j][3]+bv.y+x2.y);
    }
    pa+=__shfl_xor_sync(0xffffffffu,pa,1); pa+=__shfl_xor_sync(0xffffffffu,pa,2);
    pb+=__shfl_xor_sync(0xffffffffu,pb,1); pb+=__shfl_xor_sync(0xffffffffu,pb,2);
    if(tt==0){
        if(ra<total) lg[ra]=pa;
        if(rb<total) lg[rb]=pb;
    }
}

// fp32 128x128 GEMM, k-chunk double-buffered. MODE 0: Y=X@W+b1; MODE 2: +b2+addmat
template <int MODE>
__global__ void __launch_bounds__(256) k_gemm(
    const float* __restrict__ X,const float* __restrict__ W,
    const float* __restrict__ b1,const float* __restrict__ b2,
    float* __restrict__ Y,int total,const float* __restrict__ am){
    int row0=blockIdx.x*128;
    if(row0>=total) return;
    __shared__ float Ws[2][16][128];
    __shared__ float Xs[2][16][128];
    int t=threadIdx.x,tx=t&15,ty=t>>4;
    int tx8=tx*8,ty8=ty*8;
    int ma=t>>2,kq=t&3,mb=ma+64;
    int kwa=t>>5,nw=t&31,kwb=kwa+8;
    int rra=(row0+ma<total)?row0+ma:0;
    int rrb=(row0+mb<total)?row0+mb:0;
    const float4* X4=(const float4*)X;
    const float4* W4=(const float4*)W;
    u64 acc[8][4];
    {
        float4 q0=((const float4*)b1)[tx*2],q1=((const float4*)b1)[tx*2+1];
        if(MODE==2){
            float4 p0=((const float4*)b2)[tx*2],p1=((const float4*)b2)[tx*2+1];
            q0.x+=p0.x;q0.y+=p0.y;q0.z+=p0.z;q0.w+=p0.w;
            q1.x+=p1.x;q1.y+=p1.y;q1.z+=p1.z;q1.w+=p1.w;
        }
        u64 i0=pack2(q0.x,q0.y),i1=pack2(q0.z,q0.w),i2=pack2(q1.x,q1.y),i3=pack2(q1.z,q1.w);
#pragma unroll
        for(int r=0;r<8;r++){ acc[r][0]=i0;acc[r][1]=i1;acc[r][2]=i2;acc[r][3]=i3; }
    }
    float4 va=X4[(size_t)rra*32+kq];
    float4 vb=X4[(size_t)rrb*32+kq];
    float4 wa=W4[kwa*32+nw];
    float4 wb=W4[kwb*32+nw];
    ((float4*)&Ws[0][kwa][nw*4])[0]=wa;
    ((float4*)&Ws[0][kwb][nw*4])[0]=wb;
    Xs[0][kq*4+0][ma]=va.x; Xs[0][kq*4+1][ma]=va.y; Xs[0][kq*4+2][ma]=va.z; Xs[0][kq*4+3][ma]=va.w;
    Xs[0][kq*4+0][mb]=vb.x; Xs[0][kq*4+1][mb]=vb.y; Xs[0][kq*4+2][mb]=vb.z; Xs[0][kq*4+3][mb]=vb.w;
    __syncthreads();
#pragma unroll
    for(int c=0;c<8;c++){
        int buf=c&1;
        if(c<7){
            va=X4[(size_t)rra*32+(c+1)*4+kq];
            vb=X4[(size_t)rrb*32+(c+1)*4+kq];
            wa=W4[((c+1)*16+kwa)*32+nw];
            wb=W4[((c+1)*16+kwb)*32+nw];
        }
#pragma unroll
        for(int kk=0;kk<16;kk++){
            float4 a0=*(const float4*)&Xs[buf][kk][ty8];
            float4 a1=*(const float4*)&Xs[buf][kk][ty8+4];
            ulonglong2 b01=*(const ulonglong2*)&Ws[buf][kk][tx8];
            ulonglong2 b23=*(const ulonglong2*)&Ws[buf][kk][tx8+4];
            float av[8]={a0.x,a0.y,a0.z,a0.w,a1.x,a1.y,a1.z,a1.w};
#pragma unroll
            for(int r=0;r<8;r++){
                u64 s=splat2(av[r]);
                acc[r][0]=ffma2(s,b01.x,acc[r][0]);
                acc[r][1]=ffma2(s,b01.y,acc[r][1]);
                acc[r][2]=ffma2(s,b23.x,acc[r][2]);
                acc[r][3]=ffma2(s,b23.y,acc[r][3]);
            }
        }
        if(c<7){
            int nb=buf^1;
            ((float4*)&Ws[nb][kwa][nw*4])[0]=wa;
            ((float4*)&Ws[nb][kwb][nw*4])[0]=wb;
            Xs[nb][kq*4+0][ma]=va.x; Xs[nb][kq*4+1][ma]=va.y; Xs[nb][kq*4+2][ma]=va.z; Xs[nb][kq*4+3][ma]=va.w;
            Xs[nb][kq*4+0][mb]=vb.x; Xs[nb][kq*4+1][mb]=vb.y; Xs[nb][kq*4+2][mb]=vb.z; Xs[nb][kq*4+3][mb]=vb.w;
            __syncthreads();
        }
    }
#pragma unroll
    for(int r=0;r<8;r++){
        int row=row0+ty8+r;
        if(row<total){
            float2 v0=unpack2(acc[r][0]),v1=unpack2(acc[r][1]),v2=unpack2(acc[r][2]),v3=unpack2(acc[r][3]);
            float4 o0=make_float4(v0.x,v0.y,v1.x,v1.y);
            float4 o1=make_float4(v2.x,v2.y,v3.x,v3.y);
            if(MODE==2){
                float4 m0=((const float4*)am)[(size_t)row*32+tx*2];
                float4 m1=((const float4*)am)[(size_t)row*32+tx*2+1];
                o0.x+=m0.x;o0.y+=m0.y;o0.z+=m0.z;o0.w+=m0.w;
                o1.x+=m1.x;o1.y+=m1.y;o1.z+=m1.z;o1.w+=m1.w;
            }
            ((float4*)Y)[(size_t)row*32+tx*2]=o0;
            ((float4*)Y)[(size_t)row*32+tx*2+1]=o1;
        }
    }
}

__global__ void __launch_bounds__(256) k_agg(
    const float* __restrict__ xa,const float* __restrict__ lg,
    const int* __restrict__ oa,const int* __restrict__ sa,
    const float* __restrict__ xlpp,const float* __restrict__ xrpp,
    const float* __restrict__ attp,const float* __restrict__ bsp,
    const int* __restrict__ op,const int* __restrict__ sp,
    float* __restrict__ accap,float* __restrict__ ppo){
    int t=threadIdx.x,lane=t&31,warp=t>>5;
    int dst=blockIdx.x*8+warp;
    int e0=oa[dst],e1=oa[dst+1];
    float4 acc=make_float4(0.f,0.f,0.f,0.f);
    if(e1>e0){
        float m=-INFINITY,den=0.f;
        for(int base=e0;base<e1;base+=32){
            int e=base+lane;
            bool v=(e<e1);
            float le=v?lg[e]:-INFINITY;
            float cm=le;
#pragma unroll
            for(int o=16;o;o>>=1) cm=fmaxf(cm,__shfl_xor_sync(0xffffffffu,cm,o));
            if(cm>m){ den*=__expf(m-cm); m=cm; }
            float w=v?__expf(le-m):0.f;
#pragma unroll
            for(int o=16;o;o>>=1) w+=__shfl_xor_sync(0xffffffffu,w,o);
            den+=w;
        }
        float inv=1.f/den;
        int e=e0;
        for(;e+3<e1;e+=4){
            int s0=sa[e],s1=sa[e+1],s2=sa[e+2],s3=sa[e+3];
            float4 x0=((const float4*)xa)[(size_t)s0*32+lane];
            float4 x1=((const float4*)xa)[(size_t)s1*32+lane];
            float4 x2=((const float4*)xa)[(size_t)s2*32+lane];
            float4 x3=((const float4*)xa)[(size_t)s3*32+lane];
            float a0=__expf(lg[e]-m)*inv,a1=__expf(lg[e+1]-m)*inv;
            float a2=__expf(lg[e+2]-m)*inv,a3=__expf(lg[e+3]-m)*inv;
            acc.x+=a0*x0.x+a1*x1.x+a2*x2.x+a3*x3.x;
            acc.y+=a0*x0.y+a1*x1.y+a2*x2.y+a3*x3.y;
            acc.z+=a0*x0.z+a1*x1.z+a2*x2.z+a3*x3.z;
            acc.w+=a0*x0.w+a1*x1.w+a2*x2.w+a3*x3.w;
        }
        for(;e<e1;e++){
            float a0=__expf(lg[e]-m)*inv;
            float4 x0=((const float4*)xa)[(size_t)sa[e]*32+lane];
            acc.x+=a0*x0.x; acc.y+=a0*x0.y; acc.z+=a0*x0.z; acc.w+=a0*x0.w;
        }
    }
    ((float4*)accap)[(size_t)dst*32+lane]=acc;

    float4 attv=((const float4*)attp)[lane];
    float4 bsv=((const float4*)bsp)[lane];
    float4 xrv=((const float4*)xrpp)[(size_t)dst*32+lane];
    float m=-INFINITY,den=0.f;
    float4 pa=make_float4(0.f,0.f,0.f,0.f);
    int p0=op[dst],p1=op[dst+1];
    for(int eb=p0;eb<p1;eb+=8){
        int g=min(8,p1-eb);
        int sl=(lane<g)?sp[eb+lane]:0;
        float4 xv[8];
        float lgv[8];
#pragma unroll
        for(int i=0;i<8;i++){
            if(i<g){
                int row=__shfl_sync(0xffffffffu,sl,i);
                xv[i]=((const float4*)xlpp)[(size_t)row*32+lane];
            }
        }
#pragma unroll
        for(int i=0;i<8;i++){
            if(i<g){
                float p=lrelu(xv[i].x+xrv.x)*attv.x+lrelu(xv[i].y+xrv.y)*attv.y
                       +lrelu(xv[i].z+xrv.z)*attv.z+lrelu(xv[i].w+xrv.w)*attv.w;
#pragma unroll
                for(int o=16;o;o>>=1) p+=__shfl_xor_sync(0xffffffffu,p,o);
                lgv[i]=p;
            }
        }
        float gm=m;
#pragma unroll
        for(int i=0;i<8;i++) if(i<g) gm=fmaxf(gm,lgv[i]);
        float sc=__expf(m-gm);
        den*=sc; pa.x*=sc; pa.y*=sc; pa.z*=sc; pa.w*=sc;
#pragma unroll
        for(int i=0;i<8;i++){
            if(i<g){
                float w=__expf(lgv[i]-gm);
                den+=w;
                pa.x+=w*xv[i].x; pa.y+=w*xv[i].y; pa.z+=w*xv[i].z; pa.w+=w*xv[i].w;
            }
        }
        m=gm;
    }
    float inv2=(den>0.f)?1.f/den:0.f;
    pa.x=pa.x*inv2+bsv.x; pa.y=pa.y*inv2+bsv.y; pa.z=pa.z*inv2+bsv.z; pa.w=pa.w*inv2+bsv.w;
    ((float4*)ppo)[(size_t)dst*32+lane]=pa;
}

__global__ void __launch_bounds__(256) k_final(
    const float* __restrict__ hid,const float* __restrict__ Wl,
    const float* __restrict__ bl,float* __restrict__ out){
    extern __shared__ char sm[];
    float* Ws=(float*)sm;
    float* hs=(float*)sm+D*DOUT;
    int t=threadIdx.x,lane=t&31,warp=t>>5;
    for(int i=t;i<D*DOUT/4;i+=256) ((float4*)Ws)[i]=((const float4*)Wl)[i];
    int row0=blockIdx.x*32+warp*4;
#pragma unroll
    for(int r=0;r<4;r++){
        float4 h=((const float4*)hid)[(size_t)(row0+r)*32+lane];
        h.x=fmaxf(h.x,0.f); h.y=fmaxf(h.y,0.f); h.z=fmaxf(h.z,0.f); h.w=fmaxf(h.w,0.f);
        ((float4*)&hs[(warp*4+r)*D])[lane]=h;
    }
    __syncthreads();
    float b0=bl[lane],b1=bl[lane+32];
    float a0[4],a1[4];
#pragma unroll
    for(int r=0;r<4;r++){ a0[r]=b0; a1[r]=b1; }
    for(int k=0;k<D;k++){
        float w0=Ws[k*DOUT+lane],w1=Ws[k*DOUT+lane+32];
#pragma unroll
        for(int r=0;r<4;r++){
            float h=hs[(warp*4+r)*D+k];
            a0[r]+=h*w0; a1[r]+=h*w1;
        }
    }
#pragma unroll
    for(int r=0;r<4;r++){
        int row=row0+r;
        out[(size_t)row*DOUT+lane]=a0[r];
        out[(size_t)row*DOUT+lane+32]=a1[r];
    }
}

extern "C" void kernel_launch(void* const* d_in,const int* in_sizes,int n_in,
                              void* d_out,int out_size){
    const float* xa=(const float*)d_in[0];
    const float* xp=(const float*)d_in[1];
    const int* ea=(const int*)d_in[2];
    const int* ep=(const int*)d_in[3];
    const float* Wla=(const float*)d_in[5];
    const float* bla=(const float*)d_in[6];
    const float* Wra=(const float*)d_in[7];
    const float* bra=(const float*)d_in[8];
    const float* ata=(const float*)d_in[9];
    const float* bsa=(const float*)d_in[10];
    const float* Wlp=(const float*)d_in[11];
    const float* blp=(const float*)d_in[12];
    const float* Wrp=(const float*)d_in[13];
    const float* brp=(const float*)d_in[14];
    const float* atp=(const float*)d_in[15];
    const float* bsp=(const float*)d_in[16];
    const float* Wf=(const float*)d_in[17];
    const float* bf=(const float*)d_in[18];
    float* out=(float*)d_out;
    int Ea=in_sizes[2]/2,Ep=in_sizes[3]/2,Eb=Ea+Ep;

    void* p;
    cudaGetSymbolAddress(&p,g_xlpp); float* xlpp=(float*)p;
    cudaGetSymbolAddress(&p,g_xrpp); float* xrpp=(float*)p;
    cudaGetSymbolAddress(&p,g_xrap); float* xrap=(float*)p;
    cudaGetSymbolAddress(&p,g_hid);  float* hid=(float*)p;
    cudaGetSymbolAddress(&p,g_acc);  float* accap=(float*)p;
    cudaGetSymbolAddress(&p,g_ppo);  float* ppo=(float*)p;
    cudaGetSymbolAddress(&p,g_lg);   float* lg=(float*)p;
    cudaGetSymbolAddress(&p,g_Bf);   u64* Bf=(u64*)p;
    cudaGetSymbolAddress(&p,g_ca);   int* ca=(int*)p;
    cudaGetSymbolAddress(&p,g_cp);   int* cp=(int*)p;
    cudaGetSymbolAddress(&p,g_oa);   int* oa=(int*)p;
    cudaGetSymbolAddress(&p,g_op);   int* op=(int*)p;
    cudaGetSymbolAddress(&p,g_ua);   int* ua=(int*)p;
    cudaGetSymbolAddress(&p,g_up);   int* up=(int*)p;
    cudaGetSymbolAddress(&p,g_sa);   int* sa=(int*)p;
    cudaGetSymbolAddress(&p,g_da);   int* da=(int*)p;
    cudaGetSymbolAddress(&p,g_sp);   int* sp=(int*)p;

    cudaFuncSetAttribute(k_emma,cudaFuncAttributeMaxDynamicSharedMemorySize,53248);
    cudaFuncSetAttribute(k_final,cudaFuncAttributeMaxDynamicSharedMemorySize,49152);

    k_zero<<<(2*B+4096+255)/256,256>>>(ca,cp,Wla,Bf);
    k_hist<<<(Eb+255)/256,256>>>(ea,Ea,ca,ep,Ep,cp);
    k_scan<<<2,1024>>>(ca,oa,ua,cp,op,up);
    k_scat<<<(Eb+255)/256,256>>>(ea,Ea,ua,sa,da,ep,Ep,up,sp);
    k_gemm<0><<<B/128,256>>>(xp,Wra,bra,nullptr,xrap,B,nullptr);
    k_emma<<<(EA+127)/128,256,53248>>>(xa,Bf,bla,sa,&oa[B],da,xrap,ata,lg);
    k_gemm<0><<<(NP+127)/128,256>>>(xp,Wlp,blp,nullptr,xlpp,NP,nullptr);
    k_gemm<0><<<B/128,256>>>(xp,Wrp,brp,nullptr,xrpp,B,nullptr);
    k_agg<<<B/8,256>>>(xa,lg,oa,sa,xlpp,xrpp,atp,bsp,op,sp,accap,ppo);
    k_gemm<2><<<B/128,256>>>(accap,Wla,bla,bsa,hid,B,ppo);
    k_final<<<B/32,256,49152>>>(hid,Wf,bf,out);
}

// round 16
// speedup vs baseline: 1.3293x; 1.1307x over previous
#include <cuda_runtime.h>
#include <cuda_fp16.h>
#include <stdint.h>
#include <math.h>
#define D 128
#define DOUT 64
#define NP 30000
#define EA 300000
#define EP 960000
#define B 16384
#define NEG 0.2f
typedef unsigned long long u64;
typedef unsigned int u32;

__device__ float g_xlpp[NP*D];
__device__ float g_xrpp[B*D];
__device__ float g_xrap[B*D];
__device__ float g_hid[B*D];
__device__ float g_acc[B*D];
__device__ float g_ppo[B*D];
__device__ float g_lg[EA];
__device__ u64 g_Bf[4096];    // per-lane B fragments [ks][j][lane], fp16(Wla^T)
__device__ int g_ca[B], g_cp[B], g_oa[B+1], g_op[B+1], g_ua[B], g_up[B];
__device__ int g_sa[EA], g_da[EA], g_sp[EP];

__device__ __forceinline__ float lrelu(float x){ return x>0.f?x:NEG*x; }
__device__ __forceinline__ u64 splat2(float x){ u64 d; asm("mov.b64 %0,{%1,%1};":"=l"(d):"r"(__float_as_uint(x))); return d; }
__device__ __forceinline__ u64 pack2(float a,float b){ u64 d; asm("mov.b64 %0,{%1,%2};":"=l"(d):"r"(__float_as_uint(a)),"r"(__float_as_uint(b))); return d; }
__device__ __forceinline__ float2 unpack2(u64 u){ float2 f; asm("mov.b64 {%0,%1},%2;":"=f"(f.x),"=f"(f.y):"l"(u)); return f; }
__device__ __forceinline__ u64 ffma2(u64 a,u64 b,u64 c){ u64 d; asm("fma.rn.f32x2 %0,%1,%2,%3;":"=l"(d):"l"(a),"l"(b),"l"(c)); return d; }
__device__ __forceinline__ u32 cf2(float lo,float hi){
    __half2 h=__floats2half2_rn(lo,hi); return *(u32*)&h;
}
__device__ __forceinline__ float f16lo(u32 r){ __half2 h=*(__half2*)&r; return __low2float(h); }
__device__ __forceinline__ float f16hi(u32 r){ __half2 h=*(__half2*)&r; return __high2float(h); }
__device__ __forceinline__ void mmah(float* c,u32 a0,u32 a1,u32 a2,u32 a3,u32 b0,u32 b1){
    asm volatile("mma.sync.aligned.m16n8k16.row.col.f32.f16.f16.f32 "
        "{%0,%1,%2,%3},{%4,%5,%6,%7},{%8,%9},{%0,%1,%2,%3};"
        :"+f"(c[0]),"+f"(c[1]),"+f"(c[2]),"+f"(c[3])
        :"r"(a0),"r"(a1),"r"(a2),"r"(a3),"r"(b0),"r"(b1));
}

__global__ void k_zero(int* a,int* b,const float* W,u64* fh){
    int i=blockIdx.x*blockDim.x+threadIdx.x;
    if(i<B) a[i]=0;
    else if(i<2*B) b[i-B]=0;
    else if(i<2*B+4096){
        int idx=i-2*B;
        int ks=idx>>9, j=(idx>>5)&15, ln=idx&31;
        int n=8*j+(ln>>2), kw=ks*8+(ln&3);
        float v00=W[(2*kw)*128+n],   v01=W[(2*kw+1)*128+n];
        float v10=W[(2*kw+8)*128+n], v11=W[(2*kw+9)*128+n];
        u32 w0=cf2(v00,v01), w1=cf2(v10,v11);
        fh[idx]=(u64)w0|((u64)w1<<32);
    }
}
__global__ void k_hist(const int* ea,int Ea,int* ca,const int* ep,int Ep,int* cp){
    int i=blockIdx.x*blockDim.x+threadIdx.x;
    if(i<Ea){ int d=ea[Ea+i]; if(d<B) atomicAdd(&ca[d],1); }
    else if(i<Ea+Ep){ int d=ep[Ep+i-Ea]; if(d<B) atomicAdd(&cp[d],1); }
}
__global__ void k_scan(const int* ca,int* oa,int* ua,const int* cp,int* op,int* up){
    const int* cnt=blockIdx.x?cp:ca;
    int* off=blockIdx.x?op:oa;
    int* cur=blockIdx.x?up:ua;
    __shared__ int s[1024];
    int t=threadIdx.x,v[16],run=0;
#pragma unroll
    for(int i=0;i<16;i++){ v[i]=run; run+=cnt[t*16+i]; }
    s[t]=run; __syncthreads();
    for(int d=1;d<1024;d<<=1){
        int add=(t>=d)?s[t-d]:0; __syncthreads();
        s[t]+=add; __syncthreads();
    }
    int base=(t>0)?s[t-1]:0;
#pragma unroll
    for(int i=0;i<16;i++){ int o=base+v[i]; off[t*16+i]=o; cur[t*16+i]=o; }
    if(t==1023) off[16384]=s[1023];
}
__global__ void k_scat(const int* ea,int Ea,int* ua,int* sa,int* da,
                       const int* ep,int Ep,int* up,int* sp){
    int i=blockIdx.x*blockDim.x+threadIdx.x;
    if(i<Ea){
        int d=ea[Ea+i];
        if(d<B){ int p=atomicAdd(&ua[d],1); sa[p]=ea[i]; da[p]=d; }
    } else if(i<Ea+Ep){
        int j=i-Ea; int d=ep[Ep+j];
        if(d<B){ int p=atomicAdd(&up[d],1); sp[p]=ep[j]; }
    }
}

// edge logits via HMMA fp16 A-split (Ah*B + Al*B), K-split staging, 2 CTA/SM
__global__ void __launch_bounds__(256,2) k_emma(
    const float* __restrict__ xa,const u64* __restrict__ Bf,
    const float* __restrict__ blv,const int* __restrict__ srcs,const int* __restrict__ tot,
    const int* __restrict__ darr,const float* __restrict__ xr,
    const float* __restrict__ att,float* __restrict__ lg){
    extern __shared__ char sm[];
    u32* ah=(u32*)sm;
    u32* al=ah+4608;
    u64* bh=(u64*)(al+4608);
    int total=*tot;
    int row0=blockIdx.x*128;
    if(row0>=total) return;
    int t=threadIdx.x,wid=t>>5,lane=t&31;
    int g=lane>>2,tt=lane&3,m0=wid*16;
    int m=t>>1,q=t&1;
    int r=row0+m;
    int rr=(r<total)?srcs[r]:0;
    const float4* X4=(const float4*)xa;
    int rA=(m0+g)*36,rB=rA+288;
    float P[16][4];
#pragma unroll
    for(int j=0;j<16;j++){ P[j][0]=0.f;P[j][1]=0.f;P[j][2]=0.f;P[j][3]=0.f; }
#pragma unroll
    for(int h2=0;h2<2;h2++){
        if(h2) __syncthreads();
        {
            int base=m*36+q*16;
#pragma unroll
            for(int j=0;j<8;j++){
                float4 v=X4[(size_t)rr*32+h2*16+q*8+j];
                u32 w0=cf2(v.x,v.y),w1=cf2(v.z,v.w);
                u32 g0=cf2(v.x-f16lo(w0),v.y-f16hi(w0));
                u32 g1=cf2(v.z-f16lo(w1),v.w-f16hi(w1));
                ah[base+2*j]=w0; ah[base+2*j+1]=w1;
                al[base+2*j]=g0; al[base+2*j+1]=g1;
            }
        }
        for(int i=t;i<1024;i+=256){
            ((uint4*)bh)[i]=((const uint4*)Bf)[h2*1024+i];
        }
        __syncthreads();
#pragma unroll
        for(int ksl=0;ksl<4;ksl++){
            int kb=ksl*8+tt;
            u32 a0=ah[rA+kb],a1=ah[rB+kb],a2=ah[rA+kb+4],a3=ah[rB+kb+4];
            u32 l0=al[rA+kb],l1=al[rB+kb],l2=al[rA+kb+4],l3=al[rB+kb+4];
            const u64* bp=bh+ksl*512+lane;
#pragma unroll
            for(int j=0;j<16;j++){
                u64 bb=bp[j*32];
                mmah(P[j],a0,a1,a2,a3,(u32)bb,(u32)(bb>>32));
            }
#pragma unroll
            for(int j=0;j<16;j++){
                u64 bb=bp[j*32];
                mmah(P[j],l0,l1,l2,l3,(u32)bb,(u32)(bb>>32));
            }
        }
    }
    int ra=row0+m0+g,rb=ra+8;
    int dda=(ra<total)?darr[ra]:0,ddb=(rb<total)?darr[rb]:0;
    const float2* XRa=(const float2*)xr+(size_t)dda*64;
    const float2* XRb=(const float2*)xr+(size_t)ddb*64;
    const float2* AT=(const float2*)att;
    const float2* BL=(const float2*)blv;
    float pa=0.f,pb=0.f;
#pragma unroll
    for(int j=0;j<16;j++){
        int ci=j*4+tt;
        float2 av=AT[ci],bv=BL[ci],x1=XRa[ci],x2=XRb[ci];
        pa+=av.x*lrelu(P[j][0]+bv.x+x1.x)+av.y*lrelu(P[j][1]+bv.y+x1.y);
        pb+=av.x*lrelu(P[j][2]+bv.x+x2.x)+av.y*lrelu(P[j][3]+bv.y+x2.y);
    }
    pa+=__shfl_xor_sync(0xffffffffu,pa,1); pa+=__shfl_xor_sync(0xffffffffu,pa,2);
    pb+=__shfl_xor_sync(0xffffffffu,pb,1); pb+=__shfl_xor_sync(0xffffffffu,pb,2);
    if(tt==0){
        if(ra<total) lg[ra]=pa;
        if(rb<total) lg[rb]=pb;
    }
}

// fp32 128x128 GEMM, k-chunk double-buffered. MODE 0: Y=X@W+b1; MODE 2: +b2+addmat
template <int MODE>
__global__ void __launch_bounds__(256) k_gemm(
    const float* __restrict__ X,const float* __restrict__ W,
    const float* __restrict__ b1,const float* __restrict__ b2,
    float* __restrict__ Y,int total,const float* __restrict__ am){
    int row0=blockIdx.x*128;
    if(row0>=total) return;
    __shared__ float Ws[2][16][128];
    __shared__ float Xs[2][16][128];
    int t=threadIdx.x,tx=t&15,ty=t>>4;
    int tx8=tx*8,ty8=ty*8;
    int ma=t>>2,kq=t&3,mb=ma+64;
    int kwa=t>>5,nw=t&31,kwb=kwa+8;
    int rra=(row0+ma<total)?row0+ma:0;
    int rrb=(row0+mb<total)?row0+mb:0;
    const float4* X4=(const float4*)X;
    const float4* W4=(const float4*)W;
    u64 acc[8][4];
    {
        float4 q0=((const float4*)b1)[tx*2],q1=((const float4*)b1)[tx*2+1];
        if(MODE==2){
            float4 p0=((const float4*)b2)[tx*2],p1=((const float4*)b2)[tx*2+1];
            q0.x+=p0.x;q0.y+=p0.y;q0.z+=p0.z;q0.w+=p0.w;
            q1.x+=p1.x;q1.y+=p1.y;q1.z+=p1.z;q1.w+=p1.w;
        }
        u64 i0=pack2(q0.x,q0.y),i1=pack2(q0.z,q0.w),i2=pack2(q1.x,q1.y),i3=pack2(q1.z,q1.w);
#pragma unroll
        for(int r=0;r<8;r++){ acc[r][0]=i0;acc[r][1]=i1;acc[r][2]=i2;acc[r][3]=i3; }
    }
    float4 va=X4[(size_t)rra*32+kq];
    float4 vb=X4[(size_t)rrb*32+kq];
    float4 wa=W4[kwa*32+nw];
    float4 wb=W4[kwb*32+nw];
    ((float4*)&Ws[0][kwa][nw*4])[0]=wa;
    ((float4*)&Ws[0][kwb][nw*4])[0]=wb;
    Xs[0][kq*4+0][ma]=va.x; Xs[0][kq*4+1][ma]=va.y; Xs[0][kq*4+2][ma]=va.z; Xs[0][kq*4+3][ma]=va.w;
    Xs[0][kq*4+0][mb]=vb.x; Xs[0][kq*4+1][mb]=vb.y; Xs[0][kq*4+2][mb]=vb.z; Xs[0][kq*4+3][mb]=vb.w;
    __syncthreads();
#pragma unroll
    for(int c=0;c<8;c++){
        int buf=c&1;
        if(c<7){
            va=X4[(size_t)rra*32+(c+1)*4+kq];
            vb=X4[(size_t)rrb*32+(c+1)*4+kq];
            wa=W4[((c+1)*16+kwa)*32+nw];
            wb=W4[((c+1)*16+kwb)*32+nw];
        }
#pragma unroll
        for(int kk=0;kk<16;kk++){
            float4 a0=*(const float4*)&Xs[buf][kk][ty8];
            float4 a1=*(const float4*)&Xs[buf][kk][ty8+4];
            ulonglong2 b01=*(const ulonglong2*)&Ws[buf][kk][tx8];
            ulonglong2 b23=*(const ulonglong2*)&Ws[buf][kk][tx8+4];
            float av[8]={a0.x,a0.y,a0.z,a0.w,a1.x,a1.y,a1.z,a1.w};
#pragma unroll
            for(int r=0;r<8;r++){
                u64 s=splat2(av[r]);
                acc[r][0]=ffma2(s,b01.x,acc[r][0]);
                acc[r][1]=ffma2(s,b01.y,acc[r][1]);
                acc[r][2]=ffma2(s,b23.x,acc[r][2]);
                acc[r][3]=ffma2(s,b23.y,acc[r][3]);
            }
        }
        if(c<7){
            int nb=buf^1;
            ((float4*)&Ws[nb][kwa][nw*4])[0]=wa;
            ((float4*)&Ws[nb][kwb][nw*4])[0]=wb;
            Xs[nb][kq*4+0][ma]=va.x; Xs[nb][kq*4+1][ma]=va.y; Xs[nb][kq*4+2][ma]=va.z; Xs[nb][kq*4+3][ma]=va.w;
            Xs[nb][kq*4+0][mb]=vb.x; Xs[nb][kq*4+1][mb]=vb.y; Xs[nb][kq*4+2][mb]=vb.z; Xs[nb][kq*4+3][mb]=vb.w;
            __syncthreads();
        }
    }
#pragma unroll
    for(int r=0;r<8;r++){
        int row=row0+ty8+r;
        if(row<total){
            float2 v0=unpack2(acc[r][0]),v1=unpack2(acc[r][1]),v2=unpack2(acc[r][2]),v3=unpack2(acc[r][3]);
            float4 o0=make_float4(v0.x,v0.y,v1.x,v1.y);
            float4 o1=make_float4(v2.x,v2.y,v3.x,v3.y);
            if(MODE==2){
                float4 m0=((const float4*)am)[(size_t)row*32+tx*2];
                float4 m1=((const float4*)am)[(size_t)row*32+tx*2+1];
                o0.x+=m0.x;o0.y+=m0.y;o0.z+=m0.z;o0.w+=m0.w;
                o1.x+=m1.x;o1.y+=m1.y;o1.z+=m1.z;o1.w+=m1.w;
            }
            ((float4*)Y)[(size_t)row*32+tx*2]=o0;
            ((float4*)Y)[(size_t)row*32+tx*2+1]=o1;
        }
    }
}

__global__ void __launch_bounds__(256) k_agg(
    const float* __restrict__ xa,const float* __restrict__ lg,
    const int* __restrict__ oa,const int* __restrict__ sa,
    const float* __restrict__ xlpp,const float* __restrict__ xrpp,
    const float* __restrict__ attp,const float* __restrict__ bsp,
    const int* __restrict__ op,const int* __restrict__ sp,
    float* __restrict__ accap,float* __restrict__ ppo){
    int t=threadIdx.x,lane=t&31,warp=t>>5;
    int dst=blockIdx.x*8+warp;
    int e0=oa[dst],e1=oa[dst+1];
    float4 acc=make_float4(0.f,0.f,0.f,0.f);
    if(e1>e0){
        float m=-INFINITY,den=0.f;
        for(int base=e0;base<e1;base+=32){
            int e=base+lane;
            bool v=(e<e1);
            float le=v?lg[e]:-INFINITY;
            float cm=le;
#pragma unroll
            for(int o=16;o;o>>=1) cm=fmaxf(cm,__shfl_xor_sync(0xffffffffu,cm,o));
            if(cm>m){ den*=__expf(m-cm); m=cm; }
            float w=v?__expf(le-m):0.f;
#pragma unroll
            for(int o=16;o;o>>=1) w+=__shfl_xor_sync(0xffffffffu,w,o);
            den+=w;
        }
        float inv=1.f/den;
        int e=e0;
        for(;e+3<e1;e+=4){
            int s0=sa[e],s1=sa[e+1],s2=sa[e+2],s3=sa[e+3];
            float4 x0=((const float4*)xa)[(size_t)s0*32+lane];
            float4 x1=((const float4*)xa)[(size_t)s1*32+lane];
            float4 x2=((const float4*)xa)[(size_t)s2*32+lane];
            float4 x3=((const float4*)xa)[(size_t)s3*32+lane];
            float a0=__expf(lg[e]-m)*inv,a1=__expf(lg[e+1]-m)*inv;
            float a2=__expf(lg[e+2]-m)*inv,a3=__expf(lg[e+3]-m)*inv;
            acc.x+=a0*x0.x+a1*x1.x+a2*x2.x+a3*x3.x;
            acc.y+=a0*x0.y+a1*x1.y+a2*x2.y+a3*x3.y;
            acc.z+=a0*x0.z+a1*x1.z+a2*x2.z+a3*x3.z;
            acc.w+=a0*x0.w+a1*x1.w+a2*x2.w+a3*x3.w;
        }
        for(;e<e1;e++){
            float a0=__expf(lg[e]-m)*inv;
            float4 x0=((const float4*)xa)[(size_t)sa[e]*32+lane];
            acc.x+=a0*x0.x; acc.y+=a0*x0.y; acc.z+=a0*x0.z; acc.w+=a0*x0.w;
        }
    }
    ((float4*)accap)[(size_t)dst*32+lane]=acc;

    float4 attv=((const float4*)attp)[lane];
    float4 bsv=((const float4*)bsp)[lane];
    float4 xrv=((const float4*)xrpp)[(size_t)dst*32+lane];
    float m=-INFINITY,den=0.f;
    float4 pa=make_float4(0.f,0.f,0.f,0.f);
    int p0=op[dst],p1=op[dst+1];
    for(int eb=p0;eb<p1;eb+=8){
        int g=min(8,p1-eb);
        int sl=(lane<g)?sp[eb+lane]:0;
        float4 xv[8];
        float lgv[8];
#pragma unroll
        for(int i=0;i<8;i++){
            if(i<g){
                int row=__shfl_sync(0xffffffffu,sl,i);
                xv[i]=((const float4*)xlpp)[(size_t)row*32+lane];
            }
        }
#pragma unroll
        for(int i=0;i<8;i++){
            if(i<g){
                float p=lrelu(xv[i].x+xrv.x)*attv.x+lrelu(xv[i].y+xrv.y)*attv.y
                       +lrelu(xv[i].z+xrv.z)*attv.z+lrelu(xv[i].w+xrv.w)*attv.w;
#pragma unroll
                for(int o=16;o;o>>=1) p+=__shfl_xor_sync(0xffffffffu,p,o);
                lgv[i]=p;
            }
        }
        float gm=m;
#pragma unroll
        for(int i=0;i<8;i++) if(i<g) gm=fmaxf(gm,lgv[i]);
        float sc=__expf(m-gm);
        den*=sc; pa.x*=sc; pa.y*=sc; pa.z*=sc; pa.w*=sc;
#pragma unroll
        for(int i=0;i<8;i++){
            if(i<g){
                float w=__expf(lgv[i]-gm);
                den+=w;
                pa.x+=w*xv[i].x; pa.y+=w*xv[i].y; pa.z+=w*xv[i].z; pa.w+=w*xv[i].w;
            }
        }
        m=gm;
    }
    float inv2=(den>0.f)?1.f/den:0.f;
    pa.x=pa.x*inv2+bsv.x; pa.y=pa.y*inv2+bsv.y; pa.z=pa.z*inv2+bsv.z; pa.w=pa.w*inv2+bsv.w;
    ((float4*)ppo)[(size_t)dst*32+lane]=pa;
}

__global__ void __launch_bounds__(256) k_final(
    const float* __restrict__ hid,const float* __restrict__ Wl,
    const float* __restrict__ bl,float* __restrict__ out){
    extern __shared__ char sm[];
    float* Ws=(float*)sm;
    float* hs=(float*)sm+D*DOUT;
    int t=threadIdx.x,lane=t&31,warp=t>>5;
    for(int i=t;i<D*DOUT/4;i+=256) ((float4*)Ws)[i]=((const float4*)Wl)[i];
    int row0=blockIdx.x*32+warp*4;
#pragma unroll
    for(int r=0;r<4;r++){
        float4 h=((const float4*)hid)[(size_t)(row0+r)*32+lane];
        h.x=fmaxf(h.x,0.f); h.y=fmaxf(h.y,0.f); h.z=fmaxf(h.z,0.f); h.w=fmaxf(h.w,0.f);
        ((float4*)&hs[(warp*4+r)*D])[lane]=h;
    }
    __syncthreads();
    float b0=bl[lane],b1=bl[lane+32];
    float a0[4],a1[4];
#pragma unroll
    for(int r=0;r<4;r++){ a0[r]=b0; a1[r]=b1; }
    for(int k=0;k<D;k++){
        float w0=Ws[k*DOUT+lane],w1=Ws[k*DOUT+lane+32];
#pragma unroll
        for(int r=0;r<4;r++){
            float h=hs[(warp*4+r)*D+k];
            a0[r]+=h*w0; a1[r]+=h*w1;
        }
    }
#pragma unroll
    for(int r=0;r<4;r++){
        int row=row0+r;
        out[(size_t)row*DOUT+lane]=a0[r];
        out[(size_t)row*DOUT+lane+32]=a1[r];
    }
}

extern "C" void kernel_launch(void* const* d_in,const int* in_sizes,int n_in,
                              void* d_out,int out_size){
    const float* xa=(const float*)d_in[0];
    const float* xp=(const float*)d_in[1];
    const int* ea=(const int*)d_in[2];
    const int* ep=(const int*)d_in[3];
    const float* Wla=(const float*)d_in[5];
    const float* bla=(const float*)d_in[6];
    const float* Wra=(const float*)d_in[7];
    const float* bra=(const float*)d_in[8];
    const float* ata=(const float*)d_in[9];
    const float* bsa=(const float*)d_in[10];
    const float* Wlp=(const float*)d_in[11];
    const float* blp=(const float*)d_in[12];
    const float* Wrp=(const float*)d_in[13];
    const float* brp=(const float*)d_in[14];
    const float* atp=(const float*)d_in[15];
    const float* bsp=(const float*)d_in[16];
    const float* Wf=(const float*)d_in[17];
    const float* bf=(const float*)d_in[18];
    float* out=(float*)d_out;
    int Ea=in_sizes[2]/2,Ep=in_sizes[3]/2,Eb=Ea+Ep;

    void* p;
    cudaGetSymbolAddress(&p,g_xlpp); float* xlpp=(float*)p;
    cudaGetSymbolAddress(&p,g_xrpp); float* xrpp=(float*)p;
    cudaGetSymbolAddress(&p,g_xrap); float* xrap=(float*)p;
    cudaGetSymbolAddress(&p,g_hid);  float* hid=(float*)p;
    cudaGetSymbolAddress(&p,g_acc);  float* accap=(float*)p;
    cudaGetSymbolAddress(&p,g_ppo);  float* ppo=(float*)p;
    cudaGetSymbolAddress(&p,g_lg);   float* lg=(float*)p;
    cudaGetSymbolAddress(&p,g_Bf);   u64* Bf=(u64*)p;
    cudaGetSymbolAddress(&p,g_ca);   int* ca=(int*)p;
    cudaGetSymbolAddress(&p,g_cp);   int* cp=(int*)p;
    cudaGetSymbolAddress(&p,g_oa);   int* oa=(int*)p;
    cudaGetSymbolAddress(&p,g_op);   int* op=(int*)p;
    cudaGetSymbolAddress(&p,g_ua);   int* ua=(int*)p;
    cudaGetSymbolAddress(&p,g_up);   int* up=(int*)p;
    cudaGetSymbolAddress(&p,g_sa);   int* sa=(int*)p;
    cudaGetSymbolAddress(&p,g_da);   int* da=(int*)p;
    cudaGetSymbolAddress(&p,g_sp);   int* sp=(int*)p;

    cudaFuncSetAttribute(k_emma,cudaFuncAttributeMaxDynamicSharedMemorySize,53248);
    cudaFuncSetAttribute(k_final,cudaFuncAttributeMaxDynamicSharedMemorySize,49152);

    // fork: xlpp/xrpp GEMMs depend only on inputs -> run concurrently with
    // preprocessing + xrap + emma on a second captured stream.
    cudaStream_t s1;
    cudaEvent_t ev1, ev2;
    cudaStreamCreateWithFlags(&s1, cudaStreamNonBlocking);
    cudaEventCreateWithFlags(&ev1, cudaEventDisableTiming);
    cudaEventCreateWithFlags(&ev2, cudaEventDisableTiming);

    cudaEventRecord(ev1, 0);
    cudaStreamWaitEvent(s1, ev1, 0);
    k_gemm<0><<<(NP+127)/128,256,0,s1>>>(xp,Wlp,blp,nullptr,xlpp,NP,nullptr);
    k_gemm<0><<<B/128,256,0,s1>>>(xp,Wrp,brp,nullptr,xrpp,B,nullptr);
    cudaEventRecord(ev2, s1);

    k_zero<<<(2*B+4096+255)/256,256>>>(ca,cp,Wla,Bf);
    k_hist<<<(Eb+255)/256,256>>>(ea,Ea,ca,ep,Ep,cp);
    k_scan<<<2,1024>>>(ca,oa,ua,cp,op,up);
    k_scat<<<(Eb+255)/256,256>>>(ea,Ea,ua,sa,da,ep,Ep,up,sp);
    k_gemm<0><<<B/128,256>>>(xp,Wra,bra,nullptr,xrap,B,nullptr);
    k_emma<<<(EA+127)/128,256,53248>>>(xa,Bf,bla,sa,&oa[B],da,xrap,ata,lg);

    cudaStreamWaitEvent(0, ev2, 0);
    k_agg<<<B/8,256>>>(xa,lg,oa,sa,xlpp,xrpp,atp,bsp,op,sp,accap,ppo);
    k_gemm<2><<<B/128,256>>>(accap,Wla,bla,bsa,hid,B,ppo);
    k_final<<<B/32,256,49152>>>(hid,Wf,bf,out);

    cudaEventDestroy(ev1);
    cudaEventDestroy(ev2);
    cudaStreamDestroy(s1);
}

// round 17
// speedup vs baseline: 1.4489x; 1.0900x over previous
#include <cuda_runtime.h>
#include <cuda_fp16.h>
#include <stdint.h>
#include <math.h>
#define D 128
#define DOUT 64
#define NP 30000
#define EA 300000
#define EP 960000
#define B 16384
#define NEG 0.2f
typedef unsigned long long u64;
typedef unsigned int u32;

__device__ float g_xlpp[NP*D];
__device__ float g_xrpp[B*D];
__device__ float g_xrap[B*D];
__device__ float g_hid[B*D];
__device__ float g_acc[B*D];
__device__ float g_ppo[B*D];
__device__ float g_lg[EA];
__device__ u64 g_Bf[4096];
__device__ int g_ca[B], g_cp[B], g_oa[B+1], g_op[B+1], g_ua[B], g_up[B];
__device__ int g_sa[EA], g_da[EA], g_sp[EP];

__device__ __forceinline__ float lrelu(float x){ return x>0.f?x:NEG*x; }
__device__ __forceinline__ u64 splat2(float x){ u64 d; asm("mov.b64 %0,{%1,%1};":"=l"(d):"r"(__float_as_uint(x))); return d; }
__device__ __forceinline__ u64 pack2(float a,float b){ u64 d; asm("mov.b64 %0,{%1,%2};":"=l"(d):"r"(__float_as_uint(a)),"r"(__float_as_uint(b))); return d; }
__device__ __forceinline__ float2 unpack2(u64 u){ float2 f; asm("mov.b64 {%0,%1},%2;":"=f"(f.x),"=f"(f.y):"l"(u)); return f; }
__device__ __forceinline__ u64 ffma2(u64 a,u64 b,u64 c){ u64 d; asm("fma.rn.f32x2 %0,%1,%2,%3;":"=l"(d):"l"(a),"l"(b),"l"(c)); return d; }
__device__ __forceinline__ u32 cf2(float lo,float hi){
    __half2 h=__floats2half2_rn(lo,hi); return *(u32*)&h;
}
__device__ __forceinline__ float f16lo(u32 r){ __half2 h=*(__half2*)&r; return __low2float(h); }
__device__ __forceinline__ float f16hi(u32 r){ __half2 h=*(__half2*)&r; return __high2float(h); }
__device__ __forceinline__ void mmah(float* c,u32 a0,u32 a1,u32 a2,u32 a3,u32 b0,u32 b1){
    asm volatile("mma.sync.aligned.m16n8k16.row.col.f32.f16.f16.f32 "
        "{%0,%1,%2,%3},{%4,%5,%6,%7},{%8,%9},{%0,%1,%2,%3};"
        :"+f"(c[0]),"+f"(c[1]),"+f"(c[2]),"+f"(c[3])
        :"r"(a0),"r"(a1),"r"(a2),"r"(a3),"r"(b0),"r"(b1));
}

__global__ void k_zero(int* a,int* b,const float* W,u64* fh){
    int i=blockIdx.x*blockDim.x+threadIdx.x;
    if(i<B) a[i]=0;
    else if(i<2*B) b[i-B]=0;
    else if(i<2*B+4096){
        int idx=i-2*B;
        int ks=idx>>9, j=(idx>>5)&15, ln=idx&31;
        int n=8*j+(ln>>2), kw=ks*8+(ln&3);
        float v00=W[(2*kw)*128+n],   v01=W[(2*kw+1)*128+n];
        float v10=W[(2*kw+8)*128+n], v11=W[(2*kw+9)*128+n];
        u32 w0=cf2(v00,v01), w1=cf2(v10,v11);
        fh[idx]=(u64)w0|((u64)w1<<32);
    }
}
__global__ void k_hist(const int* ea,int Ea,int* ca,const int* ep,int Ep,int* cp){
    int i=blockIdx.x*blockDim.x+threadIdx.x;
    if(i<Ea){ int d=ea[Ea+i]; if(d<B) atomicAdd(&ca[d],1); }
    else if(i<Ea+Ep){ int d=ep[Ep+i-Ea]; if(d<B) atomicAdd(&cp[d],1); }
}
__global__ void k_scan(const int* ca,int* oa,int* ua,const int* cp,int* op,int* up){
    const int* cnt=blockIdx.x?cp:ca;
    int* off=blockIdx.x?op:oa;
    int* cur=blockIdx.x?up:ua;
    __shared__ int s[1024];
    int t=threadIdx.x,v[16],run=0;
#pragma unroll
    for(int i=0;i<16;i++){ v[i]=run; run+=cnt[t*16+i]; }
    s[t]=run; __syncthreads();
    for(int d=1;d<1024;d<<=1){
        int add=(t>=d)?s[t-d]:0; __syncthreads();
        s[t]+=add; __syncthreads();
    }
    int base=(t>0)?s[t-1]:0;
#pragma unroll
    for(int i=0;i<16;i++){ int o=base+v[i]; off[t*16+i]=o; cur[t*16+i]=o; }
    if(t==1023) off[16384]=s[1023];
}
__global__ void k_scat(const int* ea,int Ea,int* ua,int* sa,int* da,
                       const int* ep,int Ep,int* up,int* sp){
    int i=blockIdx.x*blockDim.x+threadIdx.x;
    if(i<Ea){
        int d=ea[Ea+i];
        if(d<B){ int p=atomicAdd(&ua[d],1); sa[p]=ea[i]; da[p]=d; }
    } else if(i<Ea+Ep){
        int j=i-Ea; int d=ep[Ep+j];
        if(d<B){ int p=atomicAdd(&up[d],1); sp[p]=ep[j]; }
    }
}

// edge logits via HMMA fp16 A-split (Ah*B + Al*B), K-split staging, 2 CTA/SM
__global__ void __launch_bounds__(256,2) k_emma(
    const float* __restrict__ xa,const u64* __restrict__ Bf,
    const float* __restrict__ blv,const int* __restrict__ srcs,const int* __restrict__ tot,
    const int* __restrict__ darr,const float* __restrict__ xr,
    const float* __restrict__ att,float* __restrict__ lg){
    extern __shared__ char sm[];
    u32* ah=(u32*)sm;
    u32* al=ah+4608;
    u64* bh=(u64*)(al+4608);
    int total=*tot;
    int row0=blockIdx.x*128;
    if(row0>=total) return;
    int t=threadIdx.x,wid=t>>5,lane=t&31;
    int g=lane>>2,tt=lane&3,m0=wid*16;
    int m=t>>1,q=t&1;
    int r=row0+m;
    int rr=(r<total)?srcs[r]:0;
    const float4* X4=(const float4*)xa;
    int rA=(m0+g)*36,rB=rA+288;
    float P[16][4];
#pragma unroll
    for(int j=0;j<16;j++){ P[j][0]=0.f;P[j][1]=0.f;P[j][2]=0.f;P[j][3]=0.f; }
#pragma unroll
    for(int h2=0;h2<2;h2++){
        if(h2) __syncthreads();
        {
            int base=m*36+q*16;
#pragma unroll
            for(int j=0;j<8;j++){
                float4 v=X4[(size_t)rr*32+h2*16+q*8+j];
                u32 w0=cf2(v.x,v.y),w1=cf2(v.z,v.w);
                u32 g0=cf2(v.x-f16lo(w0),v.y-f16hi(w0));
                u32 g1=cf2(v.z-f16lo(w1),v.w-f16hi(w1));
                ah[base+2*j]=w0; ah[base+2*j+1]=w1;
                al[base+2*j]=g0; al[base+2*j+1]=g1;
            }
        }
        for(int i=t;i<1024;i+=256){
            ((uint4*)bh)[i]=((const uint4*)Bf)[h2*1024+i];
        }
        __syncthreads();
#pragma unroll
        for(int ksl=0;ksl<4;ksl++){
            int kb=ksl*8+tt;
            u32 a0=ah[rA+kb],a1=ah[rB+kb],a2=ah[rA+kb+4],a3=ah[rB+kb+4];
            u32 l0=al[rA+kb],l1=al[rB+kb],l2=al[rA+kb+4],l3=al[rB+kb+4];
            const u64* bp=bh+ksl*512+lane;
#pragma unroll
            for(int j=0;j<16;j++){
                u64 bb=bp[j*32];
                mmah(P[j],a0,a1,a2,a3,(u32)bb,(u32)(bb>>32));
            }
#pragma unroll
            for(int j=0;j<16;j++){
                u64 bb=bp[j*32];
                mmah(P[j],l0,l1,l2,l3,(u32)bb,(u32)(bb>>32));
            }
        }
    }
    int ra=row0+m0+g,rb=ra+8;
    int dda=(ra<total)?darr[ra]:0,ddb=(rb<total)?darr[rb]:0;
    const float2* XRa=(const float2*)xr+(size_t)dda*64;
    const float2* XRb=(const float2*)xr+(size_t)ddb*64;
    const float2* AT=(const float2*)att;
    const float2* BL=(const float2*)blv;
    float pa=0.f,pb=0.f;
#pragma unroll
    for(int j=0;j<16;j++){
        int ci=j*4+tt;
        float2 av=AT[ci],bv=BL[ci],x1=XRa[ci],x2=XRb[ci];
        pa+=av.x*lrelu(P[j][0]+bv.x+x1.x)+av.y*lrelu(P[j][1]+bv.y+x1.y);
        pb+=av.x*lrelu(P[j][2]+bv.x+x2.x)+av.y*lrelu(P[j][3]+bv.y+x2.y);
    }
    pa+=__shfl_xor_sync(0xffffffffu,pa,1); pa+=__shfl_xor_sync(0xffffffffu,pa,2);
    pb+=__shfl_xor_sync(0xffffffffu,pb,1); pb+=__shfl_xor_sync(0xffffffffu,pb,2);
    if(tt==0){
        if(ra<total) lg[ra]=pa;
        if(rb<total) lg[rb]=pb;
    }
}

// fp32 128x128 GEMM, k-chunk double-buffered. MODE 0: Y=X@W+b1; MODE 2: +b2+addmat
template <int MODE>
__global__ void __launch_bounds__(256) k_gemm(
    const float* __restrict__ X,const float* __restrict__ W,
    const float* __restrict__ b1,const float* __restrict__ b2,
    float* __restrict__ Y,int total,const float* __restrict__ am){
    int row0=blockIdx.x*128;
    if(row0>=total) return;
    __shared__ float Ws[2][16][128];
    __shared__ float Xs[2][16][128];
    int t=threadIdx.x,tx=t&15,ty=t>>4;
    int tx8=tx*8,ty8=ty*8;
    int ma=t>>2,kq=t&3,mb=ma+64;
    int kwa=t>>5,nw=t&31,kwb=kwa+8;
    int rra=(row0+ma<total)?row0+ma:0;
    int rrb=(row0+mb<total)?row0+mb:0;
    const float4* X4=(const float4*)X;
    const float4* W4=(const float4*)W;
    u64 acc[8][4];
    {
        float4 q0=((const float4*)b1)[tx*2],q1=((const float4*)b1)[tx*2+1];
        if(MODE==2){
            float4 p0=((const float4*)b2)[tx*2],p1=((const float4*)b2)[tx*2+1];
            q0.x+=p0.x;q0.y+=p0.y;q0.z+=p0.z;q0.w+=p0.w;
            q1.x+=p1.x;q1.y+=p1.y;q1.z+=p1.z;q1.w+=p1.w;
        }
        u64 i0=pack2(q0.x,q0.y),i1=pack2(q0.z,q0.w),i2=pack2(q1.x,q1.y),i3=pack2(q1.z,q1.w);
#pragma unroll
        for(int r=0;r<8;r++){ acc[r][0]=i0;acc[r][1]=i1;acc[r][2]=i2;acc[r][3]=i3; }
    }
    float4 va=X4[(size_t)rra*32+kq];
    float4 vb=X4[(size_t)rrb*32+kq];
    float4 wa=W4[kwa*32+nw];
    float4 wb=W4[kwb*32+nw];
    ((float4*)&Ws[0][kwa][nw*4])[0]=wa;
    ((float4*)&Ws[0][kwb][nw*4])[0]=wb;
    Xs[0][kq*4+0][ma]=va.x; Xs[0][kq*4+1][ma]=va.y; Xs[0][kq*4+2][ma]=va.z; Xs[0][kq*4+3][ma]=va.w;
    Xs[0][kq*4+0][mb]=vb.x; Xs[0][kq*4+1][mb]=vb.y; Xs[0][kq*4+2][mb]=vb.z; Xs[0][kq*4+3][mb]=vb.w;
    __syncthreads();
#pragma unroll
    for(int c=0;c<8;c++){
        int buf=c&1;
        if(c<7){
            va=X4[(size_t)rra*32+(c+1)*4+kq];
            vb=X4[(size_t)rrb*32+(c+1)*4+kq];
            wa=W4[((c+1)*16+kwa)*32+nw];
            wb=W4[((c+1)*16+kwb)*32+nw];
        }
#pragma unroll
        for(int kk=0;kk<16;kk++){
            float4 a0=*(const float4*)&Xs[buf][kk][ty8];
            float4 a1=*(const float4*)&Xs[buf][kk][ty8+4];
            ulonglong2 b01=*(const ulonglong2*)&Ws[buf][kk][tx8];
            ulonglong2 b23=*(const ulonglong2*)&Ws[buf][kk][tx8+4];
            float av[8]={a0.x,a0.y,a0.z,a0.w,a1.x,a1.y,a1.z,a1.w};
#pragma unroll
            for(int r=0;r<8;r++){
                u64 s=splat2(av[r]);
                acc[r][0]=ffma2(s,b01.x,acc[r][0]);
                acc[r][1]=ffma2(s,b01.y,acc[r][1]);
                acc[r][2]=ffma2(s,b23.x,acc[r][2]);
                acc[r][3]=ffma2(s,b23.y,acc[r][3]);
            }
        }
        if(c<7){
            int nb=buf^1;
            ((float4*)&Ws[nb][kwa][nw*4])[0]=wa;
            ((float4*)&Ws[nb][kwb][nw*4])[0]=wb;
            Xs[nb][kq*4+0][ma]=va.x; Xs[nb][kq*4+1][ma]=va.y; Xs[nb][kq*4+2][ma]=va.z; Xs[nb][kq*4+3][ma]=va.w;
            Xs[nb][kq*4+0][mb]=vb.x; Xs[nb][kq*4+1][mb]=vb.y; Xs[nb][kq*4+2][mb]=vb.z; Xs[nb][kq*4+3][mb]=vb.w;
            __syncthreads();
        }
    }
#pragma unroll
    for(int r=0;r<8;r++){
        int row=row0+ty8+r;
        if(row<total){
            float2 v0=unpack2(acc[r][0]),v1=unpack2(acc[r][1]),v2=unpack2(acc[r][2]),v3=unpack2(acc[r][3]);
            float4 o0=make_float4(v0.x,v0.y,v1.x,v1.y);
            float4 o1=make_float4(v2.x,v2.y,v3.x,v3.y);
            if(MODE==2){
                float4 m0=((const float4*)am)[(size_t)row*32+tx*2];
                float4 m1=((const float4*)am)[(size_t)row*32+tx*2+1];
                o0.x+=m0.x;o0.y+=m0.y;o0.z+=m0.z;o0.w+=m0.w;
                o1.x+=m1.x;o1.y+=m1.y;o1.z+=m1.z;o1.w+=m1.w;
            }
            ((float4*)Y)[(size_t)row*32+tx*2]=o0;
            ((float4*)Y)[(size_t)row*32+tx*2+1]=o1;
        }
    }
}

// AP aggregation: softmax over precomputed logits + weighted x_aa gather
__global__ void __launch_bounds__(256) k_agg_ap(
    const float* __restrict__ xa,const float* __restrict__ lg,
    const int* __restrict__ oa,const int* __restrict__ sa,
    float* __restrict__ accap){
    int t=threadIdx.x,lane=t&31,warp=t>>5;
    int dst=blockIdx.x*8+warp;
    int e0=oa[dst],e1=oa[dst+1];
    float4 acc=make_float4(0.f,0.f,0.f,0.f);
    if(e1>e0){
        float m=-INFINITY,den=0.f;
        for(int base=e0;base<e1;base+=32){
            int e=base+lane;
            bool v=(e<e1);
            float le=v?lg[e]:-INFINITY;
            float cm=le;
#pragma unroll
            for(int o=16;o;o>>=1) cm=fmaxf(cm,__shfl_xor_sync(0xffffffffu,cm,o));
            if(cm>m){ den*=__expf(m-cm); m=cm; }
            float w=v?__expf(le-m):0.f;
#pragma unroll
            for(int o=16;o;o>>=1) w+=__shfl_xor_sync(0xffffffffu,w,o);
            den+=w;
        }
        float inv=1.f/den;
        int e=e0;
        for(;e+3<e1;e+=4){
            int s0=sa[e],s1=sa[e+1],s2=sa[e+2],s3=sa[e+3];
            float4 x0=((const float4*)xa)[(size_t)s0*32+lane];
            float4 x1=((const float4*)xa)[(size_t)s1*32+lane];
            float4 x2=((const float4*)xa)[(size_t)s2*32+lane];
            float4 x3=((const float4*)xa)[(size_t)s3*32+lane];
            float a0=__expf(lg[e]-m)*inv,a1=__expf(lg[e+1]-m)*inv;
            float a2=__expf(lg[e+2]-m)*inv,a3=__expf(lg[e+3]-m)*inv;
            acc.x+=a0*x0.x+a1*x1.x+a2*x2.x+a3*x3.x;
            acc.y+=a0*x0.y+a1*x1.y+a2*x2.y+a3*x3.y;
            acc.z+=a0*x0.z+a1*x1.z+a2*x2.z+a3*x3.z;
            acc.w+=a0*x0.w+a1*x1.w+a2*x2.w+a3*x3.w;
        }
        for(;e<e1;e++){
            float a0=__expf(lg[e]-m)*inv;
            float4 x0=((const float4*)xa)[(size_t)sa[e]*32+lane];
            acc.x+=a0*x0.x; acc.y+=a0*x0.y; acc.z+=a0*x0.z; acc.w+=a0*x0.w;
        }
    }
    ((float4*)accap)[(size_t)dst*32+lane]=acc;
}

// PP aggregation: online softmax over gathered xl_pp rows (needs only scat + xlpp/xrpp)
__global__ void __launch_bounds__(256) k_agg_pp(
    const float* __restrict__ xlpp,const float* __restrict__ xrpp,
    const float* __restrict__ attp,const float* __restrict__ bsp,
    const int* __restrict__ op,const int* __restrict__ sp,
    float* __restrict__ ppo){
    int t=threadIdx.x,lane=t&31,warp=t>>5;
    int dst=blockIdx.x*8+warp;
    float4 attv=((const float4*)attp)[lane];
    float4 bsv=((const float4*)bsp)[lane];
    float4 xrv=((const float4*)xrpp)[(size_t)dst*32+lane];
    float m=-INFINITY,den=0.f;
    float4 pa=make_float4(0.f,0.f,0.f,0.f);
    int p0=op[dst],p1=op[dst+1];
    for(int eb=p0;eb<p1;eb+=8){
        int g=min(8,p1-eb);
        int sl=(lane<g)?sp[eb+lane]:0;
        float4 xv[8];
        float lgv[8];
#pragma unroll
        for(int i=0;i<8;i++){
            if(i<g){
                int row=__shfl_sync(0xffffffffu,sl,i);
                xv[i]=((const float4*)xlpp)[(size_t)row*32+lane];
            }
        }
#pragma unroll
        for(int i=0;i<8;i++){
            if(i<g){
                float p=lrelu(xv[i].x+xrv.x)*attv.x+lrelu(xv[i].y+xrv.y)*attv.y
                       +lrelu(xv[i].z+xrv.z)*attv.z+lrelu(xv[i].w+xrv.w)*attv.w;
#pragma unroll
                for(int o=16;o;o>>=1) p+=__shfl_xor_sync(0xffffffffu,p,o);
                lgv[i]=p;
            }
        }
        float gm=m;
#pragma unroll
        for(int i=0;i<8;i++) if(i<g) gm=fmaxf(gm,lgv[i]);
        float sc=__expf(m-gm);
        den*=sc; pa.x*=sc; pa.y*=sc; pa.z*=sc; pa.w*=sc;
#pragma unroll
        for(int i=0;i<8;i++){
            if(i<g){
                float w=__expf(lgv[i]-gm);
                den+=w;
                pa.x+=w*xv[i].x; pa.y+=w*xv[i].y; pa.z+=w*xv[i].z; pa.w+=w*xv[i].w;
            }
        }
        m=gm;
    }
    float inv2=(den>0.f)?1.f/den:0.f;
    pa.x=pa.x*inv2+bsv.x; pa.y=pa.y*inv2+bsv.y; pa.z=pa.z*inv2+bsv.z; pa.w=pa.w*inv2+bsv.w;
    ((float4*)ppo)[(size_t)dst*32+lane]=pa;
}

__global__ void __launch_bounds__(256) k_final(
    const float* __restrict__ hid,const float* __restrict__ Wl,
    const float* __restrict__ bl,float* __restrict__ out){
    extern __shared__ char sm[];
    float* Ws=(float*)sm;
    float* hs=(float*)sm+D*DOUT;
    int t=threadIdx.x,lane=t&31,warp=t>>5;
    for(int i=t;i<D*DOUT/4;i+=256) ((float4*)Ws)[i]=((const float4*)Wl)[i];
    int row0=blockIdx.x*32+warp*4;
#pragma unroll
    for(int r=0;r<4;r++){
        float4 h=((const float4*)hid)[(size_t)(row0+r)*32+lane];
        h.x=fmaxf(h.x,0.f); h.y=fmaxf(h.y,0.f); h.z=fmaxf(h.z,0.f); h.w=fmaxf(h.w,0.f);
        ((float4*)&hs[(warp*4+r)*D])[lane]=h;
    }
    __syncthreads();
    float b0=bl[lane],b1=bl[lane+32];
    float a0[4],a1[4];
#pragma unroll
    for(int r=0;r<4;r++){ a0[r]=b0; a1[r]=b1; }
    for(int k=0;k<D;k++){
        float w0=Ws[k*DOUT+lane],w1=Ws[k*DOUT+lane+32];
#pragma unroll
        for(int r=0;r<4;r++){
            float h=hs[(warp*4+r)*D+k];
            a0[r]+=h*w0; a1[r]+=h*w1;
        }
    }
#pragma unroll
    for(int r=0;r<4;r++){
        int row=row0+r;
        out[(size_t)row*DOUT+lane]=a0[r];
        out[(size_t)row*DOUT+lane+32]=a1[r];
    }
}

extern "C" void kernel_launch(void* const* d_in,const int* in_sizes,int n_in,
                              void* d_out,int out_size){
    const float* xa=(const float*)d_in[0];
    const float* xp=(const float*)d_in[1];
    const int* ea=(const int*)d_in[2];
    const int* ep=(const int*)d_in[3];
    const float* Wla=(const float*)d_in[5];
    const float* bla=(const float*)d_in[6];
    const float* Wra=(const float*)d_in[7];
    const float* bra=(const float*)d_in[8];
    const float* ata=(const float*)d_in[9];
    const float* bsa=(const float*)d_in[10];
    const float* Wlp=(const float*)d_in[11];
    const float* blp=(const float*)d_in[12];
    const float* Wrp=(const float*)d_in[13];
    const float* brp=(const float*)d_in[14];
    const float* atp=(const float*)d_in[15];
    const float* bsp=(const float*)d_in[16];
    const float* Wf=(const float*)d_in[17];
    const float* bf=(const float*)d_in[18];
    float* out=(float*)d_out;
    int Ea=in_sizes[2]/2,Ep=in_sizes[3]/2,Eb=Ea+Ep;

    void* p;
    cudaGetSymbolAddress(&p,g_xlpp); float* xlpp=(float*)p;
    cudaGetSymbolAddress(&p,g_xrpp); float* xrpp=(float*)p;
    cudaGetSymbolAddress(&p,g_xrap); float* xrap=(float*)p;
    cudaGetSymbolAddress(&p,g_hid);  float* hid=(float*)p;
    cudaGetSymbolAddress(&p,g_acc);  float* accap=(float*)p;
    cudaGetSymbolAddress(&p,g_ppo);  float* ppo=(float*)p;
    cudaGetSymbolAddress(&p,g_lg);   float* lg=(float*)p;
    cudaGetSymbolAddress(&p,g_Bf);   u64* Bf=(u64*)p;
    cudaGetSymbolAddress(&p,g_ca);   int* ca=(int*)p;
    cudaGetSymbolAddress(&p,g_cp);   int* cp=(int*)p;
    cudaGetSymbolAddress(&p,g_oa);   int* oa=(int*)p;
    cudaGetSymbolAddress(&p,g_op);   int* op=(int*)p;
    cudaGetSymbolAddress(&p,g_ua);   int* ua=(int*)p;
    cudaGetSymbolAddress(&p,g_up);   int* up=(int*)p;
    cudaGetSymbolAddress(&p,g_sa);   int* sa=(int*)p;
    cudaGetSymbolAddress(&p,g_da);   int* da=(int*)p;
    cudaGetSymbolAddress(&p,g_sp);   int* sp=(int*)p;

    cudaFuncSetAttribute(k_emma,cudaFuncAttributeMaxDynamicSharedMemorySize,53248);
    cudaFuncSetAttribute(k_final,cudaFuncAttributeMaxDynamicSharedMemorySize,49152);

    cudaStream_t s1;
    cudaEvent_t evFork, evX, evScat, evPP;
    cudaStreamCreateWithFlags(&s1, cudaStreamNonBlocking);
    cudaEventCreateWithFlags(&evFork, cudaEventDisableTiming);
    cudaEventCreateWithFlags(&evX, cudaEventDisableTiming);
    cudaEventCreateWithFlags(&evScat, cudaEventDisableTiming);
    cudaEventCreateWithFlags(&evPP, cudaEventDisableTiming);

    // fork side stream at entry
    cudaEventRecord(evFork, 0);
    cudaStreamWaitEvent(s1, evFork, 0);

    // side: input-only GEMMs (xrap first: emma needs it earliest)
    k_gemm<0><<<B/128,256,0,s1>>>(xp,Wra,bra,nullptr,xrap,B,nullptr);
    cudaEventRecord(evX, s1);
    k_gemm<0><<<(NP+127)/128,256,0,s1>>>(xp,Wlp,blp,nullptr,xlpp,NP,nullptr);
    k_gemm<0><<<B/128,256,0,s1>>>(xp,Wrp,brp,nullptr,xrpp,B,nullptr);

    // main: preprocessing
    k_zero<<<(2*B+4096+255)/256,256>>>(ca,cp,Wla,Bf);
    k_hist<<<(Eb+255)/256,256>>>(ea,Ea,ca,ep,Ep,cp);
    k_scan<<<2,1024>>>(ca,oa,ua,cp,op,up);
    k_scat<<<(Eb+255)/256,256>>>(ea,Ea,ua,sa,da,ep,Ep,up,sp);
    cudaEventRecord(evScat, 0);

    // side: PP aggregation (needs scat + xlpp/xrpp), concurrent with emma
    cudaStreamWaitEvent(s1, evScat, 0);
    k_agg_pp<<<B/8,256,0,s1>>>(xlpp,xrpp,atp,bsp,op,sp,ppo);
    cudaEventRecord(evPP, s1);

    // main: emma (needs scat + xrap), then AP aggregation
    cudaStreamWaitEvent(0, evX, 0);
    k_emma<<<(EA+127)/128,256,53248>>>(xa,Bf,bla,sa,&oa[B],da,xrap,ata,lg);
    k_agg_ap<<<B/8,256>>>(xa,lg,oa,sa,accap);

    // join: hid = accap @ Wla + bla + bsa + ppo
    cudaStreamWaitEvent(0, evPP, 0);
    k_gemm<2><<<B/128,256>>>(accap,Wla,bla,bsa,hid,B,ppo);
    k_final<<<B/32,256,49152>>>(hid,Wf,bf,out);

    cudaEventDestroy(evFork);
    cudaEventDestroy(evX);
    cudaEventDestroy(evScat);
    cudaEventDestroy(evPP);
    cudaStreamDestroy(s1);
}